// round 7
// baseline (speedup 1.0000x reference)
#include <cuda_runtime.h>
#include <cuda_bf16.h>
#include <math.h>
#include <stdint.h>

// Problem constants
#define BATCH 2
#define SEQ   2048
#define DIM   4096
#define NHEAD 32
#define HDIM  128
#define MROWS (BATCH * SEQ)   // 4096
#define NELEM (MROWS * DIM)   // 16777216

// fp32 scratch (QKV GEMM outputs / rope inputs)
__device__ float g_q[NELEM];
__device__ float g_k[NELEM];
__device__ float g_v[NELEM];
// bf16 hi arrays (hh pass / flash)
__device__ __nv_bfloat16 g_xh[NELEM];
__device__ __nv_bfloat16 g_wqh[NELEM], g_wkh[NELEM], g_wvh[NELEM], g_woh[NELEM];
__device__ __nv_bfloat16 g_qh[NELEM], g_ql[NELEM];
__device__ __nv_bfloat16 g_kh[NELEM], g_kl[NELEM];
__device__ __nv_bfloat16 g_vh[NELEM], g_vl[NELEM];
__device__ __nv_bfloat16 g_ah[NELEM];
// fp8 arrays for cross terms (e4m3)
__device__ uint8_t g_x8h[NELEM],  g_x8l[NELEM];
__device__ uint8_t g_wq8h[NELEM], g_wq8l[NELEM];
__device__ uint8_t g_wk8h[NELEM], g_wk8l[NELEM];
__device__ uint8_t g_wv8h[NELEM], g_wv8l[NELEM];
__device__ uint8_t g_wo8h[NELEM], g_wo8l[NELEM];
__device__ uint8_t g_a8h[NELEM],  g_a8l[NELEM];

// Scales: act-lo x 2^8; wgt-hi x 2^5; wgt-lo x 2^13. Cross product scale 2^-13.
#define ACT_LO_SCALE 256.0f
#define WGT_HI_SCALE 32.0f
#define WGT_LO_SCALE 8192.0f
#define CROSS_UNSCALE 0.0001220703125f   // 2^-13

// ---------------------------------------------------------------------------
// Helpers
// ---------------------------------------------------------------------------
__device__ __forceinline__ uint32_t smem_u32(const void* p) {
    uint32_t a;
    asm("{ .reg .u64 t; cvta.to.shared.u64 t, %1; cvt.u32.u64 %0, t; }"
        : "=r"(a) : "l"(p));
    return a;
}

__device__ __forceinline__ void cpa16(uint32_t dst, const void* src) {
    asm volatile("cp.async.cg.shared.global [%0], [%1], 16;"
                 :: "r"(dst), "l"(src));
}
#define CP_COMMIT() asm volatile("cp.async.commit_group;" ::: "memory")
#define CP_WAIT(n)  asm volatile("cp.async.wait_group " #n ";" ::: "memory")

__device__ __forceinline__ void ldsm4(uint32_t addr, uint32_t& r0, uint32_t& r1,
                                      uint32_t& r2, uint32_t& r3) {
    asm volatile("ldmatrix.sync.aligned.m8n8.x4.shared.b16 {%0,%1,%2,%3}, [%4];"
                 : "=r"(r0), "=r"(r1), "=r"(r2), "=r"(r3) : "r"(addr));
}
__device__ __forceinline__ void ldsm4t(uint32_t addr, uint32_t& r0, uint32_t& r1,
                                       uint32_t& r2, uint32_t& r3) {
    asm volatile("ldmatrix.sync.aligned.m8n8.x4.trans.shared.b16 {%0,%1,%2,%3}, [%4];"
                 : "=r"(r0), "=r"(r1), "=r"(r2), "=r"(r3) : "r"(addr));
}

__device__ __forceinline__ void mma_bf16(float* c, const uint32_t* a,
                                         const uint32_t* b) {
    asm volatile(
        "mma.sync.aligned.m16n8k16.row.col.f32.bf16.bf16.f32 "
        "{%0,%1,%2,%3}, {%4,%5,%6,%7}, {%8,%9}, {%0,%1,%2,%3};"
        : "+f"(c[0]), "+f"(c[1]), "+f"(c[2]), "+f"(c[3])
        : "r"(a[0]), "r"(a[1]), "r"(a[2]), "r"(a[3]), "r"(b[0]), "r"(b[1]));
}
__device__ __forceinline__ void mma_bf16_2(float* c, const uint32_t* a,
                                           uint32_t b0, uint32_t b1) {
    asm volatile(
        "mma.sync.aligned.m16n8k16.row.col.f32.bf16.bf16.f32 "
        "{%0,%1,%2,%3}, {%4,%5,%6,%7}, {%8,%9}, {%0,%1,%2,%3};"
        : "+f"(c[0]), "+f"(c[1]), "+f"(c[2]), "+f"(c[3])
        : "r"(a[0]), "r"(a[1]), "r"(a[2]), "r"(a[3]), "r"(b0), "r"(b1));
}
__device__ __forceinline__ void mma_fp8(float* c, const uint32_t* a,
                                        uint32_t b0, uint32_t b1) {
    asm volatile(
        "mma.sync.aligned.m16n8k32.row.col.f32.e4m3.e4m3.f32 "
        "{%0,%1,%2,%3}, {%4,%5,%6,%7}, {%8,%9}, {%0,%1,%2,%3};"
        : "+f"(c[0]), "+f"(c[1]), "+f"(c[2]), "+f"(c[3])
        : "r"(a[0]), "r"(a[1]), "r"(a[2]), "r"(a[3]), "r"(b0), "r"(b1));
}

__device__ __forceinline__ uint32_t packbf(__nv_bfloat16 a, __nv_bfloat16 b) {
    return ((uint32_t)__bfloat16_as_ushort(b) << 16) | __bfloat16_as_ushort(a);
}
__device__ __forceinline__ void split2(float x, float y, uint32_t& hi, uint32_t& lo) {
    __nv_bfloat16 hx = __float2bfloat16(x);
    __nv_bfloat16 hy = __float2bfloat16(y);
    hi = packbf(hx, hy);
    lo = packbf(__float2bfloat16(x - __bfloat162float(hx)),
                __float2bfloat16(y - __bfloat162float(hy)));
}
// pack 2 floats -> 2 e4m3 (elem0 in low byte)
__device__ __forceinline__ uint16_t fp8x2(float e0, float e1) {
    uint16_t r;
    asm("cvt.rn.satfinite.e4m3x2.f32 %0, %1, %2;" : "=h"(r) : "f"(e1), "f"(e0));
    return r;
}
__device__ __forceinline__ uint32_t fp8x4(float a, float b, float c, float d) {
    return ((uint32_t)fp8x2(c, d) << 16) | fp8x2(a, b);
}

// ---------------------------------------------------------------------------
// Split kernels
// ---------------------------------------------------------------------------
__global__ __launch_bounds__(256) void split_act(const float* __restrict__ src,
                                                 __nv_bfloat16* __restrict__ dh,
                                                 uint8_t* __restrict__ d8h,
                                                 uint8_t* __restrict__ d8l,
                                                 int n4) {
    int i = blockIdx.x * blockDim.x + threadIdx.x;
    if (i >= n4) return;
    float4 v = ((const float4*)src)[i];
    float hx = __bfloat162float(__float2bfloat16(v.x));
    float hy = __bfloat162float(__float2bfloat16(v.y));
    float hz = __bfloat162float(__float2bfloat16(v.z));
    float hw = __bfloat162float(__float2bfloat16(v.w));
    ((uint2*)dh)[i] = make_uint2(packbf(__float2bfloat16(v.x), __float2bfloat16(v.y)),
                                 packbf(__float2bfloat16(v.z), __float2bfloat16(v.w)));
    ((uint32_t*)d8h)[i] = fp8x4(v.x, v.y, v.z, v.w);
    ((uint32_t*)d8l)[i] = fp8x4((v.x - hx) * ACT_LO_SCALE, (v.y - hy) * ACT_LO_SCALE,
                                (v.z - hz) * ACT_LO_SCALE, (v.w - hw) * ACT_LO_SCALE);
}

__global__ __launch_bounds__(256) void split_wgt(const float* __restrict__ src,
                                                 __nv_bfloat16* __restrict__ dh,
                                                 uint8_t* __restrict__ d8h,
                                                 uint8_t* __restrict__ d8l,
                                                 int n4) {
    int i = blockIdx.x * blockDim.x + threadIdx.x;
    if (i >= n4) return;
    float4 v = ((const float4*)src)[i];
    float hx = __bfloat162float(__float2bfloat16(v.x));
    float hy = __bfloat162float(__float2bfloat16(v.y));
    float hz = __bfloat162float(__float2bfloat16(v.z));
    float hw = __bfloat162float(__float2bfloat16(v.w));
    ((uint2*)dh)[i] = make_uint2(packbf(__float2bfloat16(v.x), __float2bfloat16(v.y)),
                                 packbf(__float2bfloat16(v.z), __float2bfloat16(v.w)));
    ((uint32_t*)d8h)[i] = fp8x4(v.x * WGT_HI_SCALE, v.y * WGT_HI_SCALE,
                                v.z * WGT_HI_SCALE, v.w * WGT_HI_SCALE);
    ((uint32_t*)d8l)[i] = fp8x4((v.x - hx) * WGT_LO_SCALE, (v.y - hy) * WGT_LO_SCALE,
                                (v.z - hz) * WGT_LO_SCALE, (v.w - hw) * WGT_LO_SCALE);
}

// ---------------------------------------------------------------------------
// GEMM v4 (NT): C = A*B^T.  hh pass in bf16 (m16n8k16), cross terms in fp8
// (m16n8k32, concat-K [a8h|a8l] x [b8l|b8h], single 2^-13 scale).
// 128x128 tile, BK=32, 8 warps (2x4, warp tile 64x32), 4-stage cp.async.
// ---------------------------------------------------------------------------
#define BM 128
#define BN 128
#define BK 32
#define NKC (DIM / BK)   // 128
#define PITCHB 80

#define OFF_AH 0
#define OFF_AX 10240
#define OFF_BH 20480
#define OFF_BX 30720
#define STAGE_BYTES 40960
#define GEMM_SMEM (4 * STAGE_BYTES)   // 163840

__global__ __launch_bounds__(256, 1)
void gemm_hx(const __nv_bfloat16* __restrict__ Ah,
             const uint8_t* __restrict__ A8h, const uint8_t* __restrict__ A8l,
             const __nv_bfloat16* __restrict__ Bh,
             const uint8_t* __restrict__ B8l, const uint8_t* __restrict__ B8h,
             float* __restrict__ C) {
    extern __shared__ char smem_raw[];
    const uint32_t sbase = smem_u32(smem_raw);
    const int tid  = threadIdx.x;
    const int wid  = tid >> 5;
    const int lane = tid & 31;
    const int wm   = wid >> 2;
    const int wn   = wid & 3;
    const int m0   = blockIdx.y * BM;
    const int n0   = blockIdx.x * BN;

    const char* Ahb  = (const char*)(Ah  + (size_t)m0 * DIM);
    const char* A8hb = (const char*)(A8h + (size_t)m0 * DIM);
    const char* A8lb = (const char*)(A8l + (size_t)m0 * DIM);
    const char* Bhb  = (const char*)(Bh  + (size_t)n0 * DIM);
    const char* B8lb = (const char*)(B8l + (size_t)n0 * DIM);
    const char* B8hb = (const char*)(B8h + (size_t)n0 * DIM);

    float accH[4][4][4], accX[4][4][4];
#pragma unroll
    for (int i = 0; i < 4; i++)
#pragma unroll
        for (int j = 0; j < 4; j++)
#pragma unroll
            for (int k = 0; k < 4; k++) { accH[i][j][k] = 0.0f; accX[i][j][k] = 0.0f; }

#define ISSUE(kc, stg)                                                        \
    {                                                                         \
        uint32_t sb = sbase + (uint32_t)(stg) * STAGE_BYTES;                  \
        _Pragma("unroll")                                                     \
        for (int u = 0; u < 2; u++) {                                         \
            int seg = tid + u * 256;                                          \
            int row = seg >> 2;                                               \
            int q   = seg & 3;                                                \
            uint32_t so = (uint32_t)row * PITCHB + q * 16;                    \
            /* bf16 hi tiles: 64B/row */                                      \
            cpa16(sb + OFF_AH + so, Ahb + (size_t)row * (DIM * 2) + (kc) * 64 + q * 16); \
            cpa16(sb + OFF_BH + so, Bhb + (size_t)row * (DIM * 2) + (kc) * 64 + q * 16); \
            /* fp8 aug tiles: [h8|l8] for A, [l8|h8] for B */                 \
            const char* asrc = (q < 2)                                        \
                ? A8hb + (size_t)row * DIM + (kc) * 32 + q * 16               \
                : A8lb + (size_t)row * DIM + (kc) * 32 + (q - 2) * 16;        \
            cpa16(sb + OFF_AX + so, asrc);                                    \
            const char* bsrc = (q < 2)                                        \
                ? B8lb + (size_t)row * DIM + (kc) * 32 + q * 16               \
                : B8hb + (size_t)row * DIM + (kc) * 32 + (q - 2) * 16;        \
            cpa16(sb + OFF_BX + so, bsrc);                                    \
        }                                                                     \
        CP_COMMIT();                                                          \
    }

    const uint32_t lm_off = (uint32_t)(lane & 15) * PITCHB + (lane >> 4) * 16;
    const uint32_t aAdr0 = (uint32_t)(wm * 64) * PITCHB + lm_off;
    const uint32_t bAdr0 = (uint32_t)(wn * 32) * PITCHB + lm_off;

    ISSUE(0, 0);
    ISSUE(1, 1);
    ISSUE(2, 2);

    for (int kc = 0; kc < NKC; kc++) {
        CP_WAIT(2);
        __syncthreads();
        if (kc + 3 < NKC) { ISSUE(kc + 3, (kc + 3) & 3); }
        else { CP_COMMIT(); }

        const uint32_t stg = sbase + (uint32_t)(kc & 3) * STAGE_BYTES;
        const uint32_t aH = stg + OFF_AH + aAdr0;
        const uint32_t aX = stg + OFF_AX + aAdr0;
        const uint32_t bH = stg + OFF_BH + bAdr0;
        const uint32_t bX = stg + OFF_BX + bAdr0;

        // ---- bf16 hh pass ----
#pragma unroll
        for (int s = 0; s < 2; s++) {
            uint32_t aF[4][4], bF[4][2];
#pragma unroll
            for (int mi = 0; mi < 4; mi++)
                ldsm4(aH + mi * (16 * PITCHB) + s * 32,
                      aF[mi][0], aF[mi][1], aF[mi][2], aF[mi][3]);
#pragma unroll
            for (int nj = 0; nj < 2; nj++) {
                uint32_t r0, r1, r2, r3;
                ldsm4(bH + nj * (16 * PITCHB) + s * 32, r0, r1, r2, r3);
                bF[nj * 2][0] = r0; bF[nj * 2 + 1][0] = r1;
                bF[nj * 2][1] = r2; bF[nj * 2 + 1][1] = r3;
            }
#pragma unroll
            for (int mi = 0; mi < 4; mi++)
#pragma unroll
                for (int nf = 0; nf < 4; nf++)
                    mma_bf16(accH[mi][nf], aF[mi], bF[nf]);
        }

        // ---- fp8 cross pass (concat-K, k32 per MMA) ----
#pragma unroll
        for (int s = 0; s < 2; s++) {
            uint32_t a8[4][4], b8[4][2];
#pragma unroll
            for (int mi = 0; mi < 4; mi++)
                ldsm4(aX + mi * (16 * PITCHB) + s * 32,
                      a8[mi][0], a8[mi][1], a8[mi][2], a8[mi][3]);
#pragma unroll
            for (int nj = 0; nj < 2; nj++) {
                uint32_t r0, r1, r2, r3;
                ldsm4(bX + nj * (16 * PITCHB) + s * 32, r0, r1, r2, r3);
                b8[nj * 2][0] = r0; b8[nj * 2 + 1][0] = r1;
                b8[nj * 2][1] = r2; b8[nj * 2 + 1][1] = r3;
            }
#pragma unroll
            for (int mi = 0; mi < 4; mi++)
#pragma unroll
                for (int nf = 0; nf < 4; nf++)
                    mma_fp8(accX[mi][nf], a8[mi], b8[nf][0], b8[nf][1]);
        }
        __syncthreads();
    }

#pragma unroll
    for (int mi = 0; mi < 4; mi++) {
#pragma unroll
        for (int nf = 0; nf < 4; nf++) {
            int row = m0 + wm * 64 + mi * 16 + (lane >> 2);
            int col = n0 + wn * 32 + nf * 8 + (lane & 3) * 2;
            *(float2*)&C[(size_t)row * DIM + col] = make_float2(
                accH[mi][nf][0] + accX[mi][nf][0] * CROSS_UNSCALE,
                accH[mi][nf][1] + accX[mi][nf][1] * CROSS_UNSCALE);
            *(float2*)&C[(size_t)(row + 8) * DIM + col] = make_float2(
                accH[mi][nf][2] + accX[mi][nf][2] * CROSS_UNSCALE,
                accH[mi][nf][3] + accX[mi][nf][3] * CROSS_UNSCALE);
        }
    }
#undef ISSUE
}

// ---------------------------------------------------------------------------
// RoPE + split (bf16 hi/lo for flash)
// ---------------------------------------------------------------------------
__global__ __launch_bounds__(256) void rope_split_kernel(
    const float* __restrict__ fcos, const float* __restrict__ fsin) {
    int idx = blockIdx.x * blockDim.x + threadIdx.x;
    int j = idx & 63;
    int h = (idx >> 6) & 31;
    int s = (idx >> 11) & 2047;
    int b = idx >> 22;
    const float scale = 0.08838834764831845f;

    float c = fcos[s * 64 + j];
    float sn = fsin[s * 64 + j];
    size_t base = ((size_t)(b * SEQ + s)) * DIM + h * HDIM + 2 * j;

    float2 q2 = *(const float2*)&g_q[base];
    float2 k2 = *(const float2*)&g_k[base];
    float2 v2 = *(const float2*)&g_v[base];

    float qr = (q2.x * c - q2.y * sn) * scale;
    float qi = (q2.x * sn + q2.y * c) * scale;
    float kr = k2.x * c - k2.y * sn;
    float ki = k2.x * sn + k2.y * c;

    uint32_t hi, lo;
    split2(qr, qi, hi, lo);
    *(uint32_t*)&g_qh[base] = hi;
    *(uint32_t*)&g_ql[base] = lo;
    split2(kr, ki, hi, lo);
    *(uint32_t*)&g_kh[base] = hi;
    *(uint32_t*)&g_kl[base] = lo;
    split2(v2.x, v2.y, hi, lo);
    *(uint32_t*)&g_vh[base] = hi;
    *(uint32_t*)&g_vl[base] = lo;
}

// ---------------------------------------------------------------------------
// Flash attention (bf16x3, unchanged core from R5; epilogue emits fp8 split)
// ---------------------------------------------------------------------------
#define FPITCH 272
#define FQH 0
#define FQL (128 * FPITCH)
#define FSTG0 (2 * 128 * FPITCH)
#define FKH 0
#define FKL (64 * FPITCH)
#define FVH (128 * FPITCH)
#define FVL (192 * FPITCH)
#define FSTAGE (256 * FPITCH)
#define FLASH_SMEM (FSTG0 + 2 * FSTAGE)

__global__ __launch_bounds__(256)
void flash_mma() {
    extern __shared__ char smem_raw[];
    const uint32_t sbase = smem_u32(smem_raw);
    const int tid  = threadIdx.x;
    const int w    = tid >> 5;
    const int lane = tid & 31;
    const int qt = blockIdx.x;
    const int h  = blockIdx.y;
    const int b  = blockIdx.z;
    const int q0 = qt * 128;
    const size_t hoff = (size_t)h * HDIM;

    const char* khb = (const char*)g_kh;
    const char* klb = (const char*)g_kl;
    const char* vhb = (const char*)g_vh;
    const char* vlb = (const char*)g_vl;

    {
        const char* qhb = (const char*)g_qh;
        const char* qlb = (const char*)g_ql;
        for (int i = tid; i < 2048; i += 256) {
            int r = i >> 4, sg = (i & 15) * 16;
            size_t go = ((size_t)(b * SEQ + q0 + r) * DIM + hoff) * 2 + sg;
            uint32_t so = (uint32_t)r * FPITCH + sg;
            *(uint4*)(smem_raw + FQH + so) = *(const uint4*)(qhb + go);
            *(uint4*)(smem_raw + FQL + so) = *(const uint4*)(qlb + go);
        }
    }

#define LOADKV(t, stg)                                                        \
    {                                                                         \
        uint32_t sp = sbase + FSTG0 + (uint32_t)(stg) * FSTAGE;               \
        const int j0 = (t) * 64;                                              \
        _Pragma("unroll")                                                     \
        for (int u = 0; u < 4; u++) {                                         \
            int seg = tid + u * 256;                                          \
            int row = seg >> 4;                                               \
            int off = (seg & 15) * 16;                                        \
            uint32_t so = (uint32_t)row * FPITCH + off;                       \
            size_t go = ((size_t)(b * SEQ + j0 + row) * DIM + hoff) * 2 + off;\
            cpa16(sp + FKH + so, khb + go);                                   \
            cpa16(sp + FKL + so, klb + go);                                   \
            cpa16(sp + FVH + so, vhb + go);                                   \
            cpa16(sp + FVL + so, vlb + go);                                   \
        }                                                                     \
        CP_COMMIT();                                                          \
    }

    LOADKV(0, 0);

    float o[16][4];
#pragma unroll
    for (int nf = 0; nf < 16; nf++)
#pragma unroll
        for (int k = 0; k < 4; k++) o[nf][k] = 0.0f;
    float m0 = -INFINITY, m1 = -INFINITY, l0s = 0.0f, l1s = 0.0f;

    const uint32_t lmA = (uint32_t)(lane & 15) * FPITCH + (lane >> 4) * 16;
    const uint32_t qAdr = sbase + (uint32_t)(w * 16) * FPITCH + lmA;
    const uint32_t lmV = (uint32_t)(((lane >> 3) & 1) * 8 + (lane & 7)) * FPITCH
                         + (lane >> 4) * 16;

    for (int t = 0; t < 32; t++) {
        const int cur = t & 1;
        CP_WAIT(0);
        __syncthreads();
        if (t + 1 < 32) { LOADKV(t + 1, 1 - cur); }

        const uint32_t stg = sbase + FSTG0 + (uint32_t)cur * FSTAGE;

        float sc[8][4];
#pragma unroll
        for (int nf = 0; nf < 8; nf++)
#pragma unroll
            for (int k = 0; k < 4; k++) sc[nf][k] = 0.0f;

#pragma unroll
        for (int ks = 0; ks < 8; ks++) {
            uint32_t qh[4], ql[4];
            ldsm4(qAdr + FQH + ks * 32, qh[0], qh[1], qh[2], qh[3]);
            ldsm4(qAdr + FQL + ks * 32, ql[0], ql[1], ql[2], ql[3]);
#pragma unroll
            for (int nfp = 0; nfp < 4; nfp++) {
                uint32_t kAdr = stg + (uint32_t)(nfp * 16) * FPITCH + lmA + ks * 32;
                uint32_t kh0, kh1, kh2, kh3, kl0, kl1, kl2, kl3;
                ldsm4(kAdr + FKH, kh0, kh1, kh2, kh3);
                ldsm4(kAdr + FKL, kl0, kl1, kl2, kl3);
                mma_bf16_2(sc[nfp * 2],     qh, kh0, kh2);
                mma_bf16_2(sc[nfp * 2 + 1], qh, kh1, kh3);
                mma_bf16_2(sc[nfp * 2],     qh, kl0, kl2);
                mma_bf16_2(sc[nfp * 2 + 1], qh, kl1, kl3);
                mma_bf16_2(sc[nfp * 2],     ql, kh0, kh2);
                mma_bf16_2(sc[nfp * 2 + 1], ql, kh1, kh3);
            }
        }

        float mx0 = -INFINITY, mx1 = -INFINITY;
#pragma unroll
        for (int nf = 0; nf < 8; nf++) {
            mx0 = fmaxf(mx0, fmaxf(sc[nf][0], sc[nf][1]));
            mx1 = fmaxf(mx1, fmaxf(sc[nf][2], sc[nf][3]));
        }
        mx0 = fmaxf(mx0, __shfl_xor_sync(0xffffffffu, mx0, 1));
        mx0 = fmaxf(mx0, __shfl_xor_sync(0xffffffffu, mx0, 2));
        mx1 = fmaxf(mx1, __shfl_xor_sync(0xffffffffu, mx1, 1));
        mx1 = fmaxf(mx1, __shfl_xor_sync(0xffffffffu, mx1, 2));

        float mn0 = fmaxf(m0, mx0), mn1 = fmaxf(m1, mx1);
        float a0 = __expf(m0 - mn0), a1 = __expf(m1 - mn1);
        float rs0 = 0.0f, rs1 = 0.0f;
#pragma unroll
        for (int nf = 0; nf < 8; nf++) {
            sc[nf][0] = __expf(sc[nf][0] - mn0);
            sc[nf][1] = __expf(sc[nf][1] - mn0);
            sc[nf][2] = __expf(sc[nf][2] - mn1);
            sc[nf][3] = __expf(sc[nf][3] - mn1);
            rs0 += sc[nf][0] + sc[nf][1];
            rs1 += sc[nf][2] + sc[nf][3];
        }
        rs0 += __shfl_xor_sync(0xffffffffu, rs0, 1);
        rs0 += __shfl_xor_sync(0xffffffffu, rs0, 2);
        rs1 += __shfl_xor_sync(0xffffffffu, rs1, 1);
        rs1 += __shfl_xor_sync(0xffffffffu, rs1, 2);
        l0s = l0s * a0 + rs0;
        l1s = l1s * a1 + rs1;
        m0 = mn0; m1 = mn1;
#pragma unroll
        for (int nf = 0; nf < 16; nf++) {
            o[nf][0] *= a0; o[nf][1] *= a0;
            o[nf][2] *= a1; o[nf][3] *= a1;
        }

        uint32_t ph[4][4], pl[4][4];
#pragma unroll
        for (int ks = 0; ks < 4; ks++) {
            split2(sc[2 * ks][0],     sc[2 * ks][1],     ph[ks][0], pl[ks][0]);
            split2(sc[2 * ks][2],     sc[2 * ks][3],     ph[ks][1], pl[ks][1]);
            split2(sc[2 * ks + 1][0], sc[2 * ks + 1][1], ph[ks][2], pl[ks][2]);
            split2(sc[2 * ks + 1][2], sc[2 * ks + 1][3], ph[ks][3], pl[ks][3]);
        }

#pragma unroll
        for (int nfp = 0; nfp < 8; nfp++) {
#pragma unroll
            for (int ks = 0; ks < 4; ks++) {
                uint32_t vAdr = stg + (uint32_t)(ks * 16) * FPITCH + lmV + nfp * 32;
                uint32_t vh0, vh1, vh2, vh3, vl0, vl1, vl2, vl3;
                ldsm4t(vAdr + FVH, vh0, vh1, vh2, vh3);
                ldsm4t(vAdr + FVL, vl0, vl1, vl2, vl3);
                mma_bf16_2(o[nfp * 2],     ph[ks], vh0, vh1);
                mma_bf16_2(o[nfp * 2 + 1], ph[ks], vh2, vh3);
                mma_bf16_2(o[nfp * 2],     ph[ks], vl0, vl1);
                mma_bf16_2(o[nfp * 2 + 1], ph[ks], vl2, vl3);
                mma_bf16_2(o[nfp * 2],     pl[ks], vh0, vh1);
                mma_bf16_2(o[nfp * 2 + 1], pl[ks], vh2, vh3);
            }
        }
        __syncthreads();
    }

    // ---- normalize + emit bf16-hi / fp8-hi / fp8-lo(x256) for O-GEMM ----
    const float inv0 = 1.0f / l0s;
    const float inv1 = 1.0f / l1s;
    const int g = lane >> 2;
    const int tq = lane & 3;
    const int row0 = q0 + w * 16 + g;
    size_t base0 = ((size_t)(b * SEQ + row0)) * DIM + hoff + tq * 2;
    size_t base1 = base0 + (size_t)8 * DIM;
#pragma unroll
    for (int nf = 0; nf < 16; nf++) {
        float v0 = o[nf][0] * inv0, v1 = o[nf][1] * inv0;
        float w0 = o[nf][2] * inv1, w1 = o[nf][3] * inv1;
        float h0 = __bfloat162float(__float2bfloat16(v0));
        float h1 = __bfloat162float(__float2bfloat16(v1));
        float g0 = __bfloat162float(__float2bfloat16(w0));
        float g1 = __bfloat162float(__float2bfloat16(w1));
        *(uint32_t*)&g_ah[base0 + nf * 8] =
            packbf(__float2bfloat16(v0), __float2bfloat16(v1));
        *(uint16_t*)&g_a8h[base0 + nf * 8] = fp8x2(v0, v1);
        *(uint16_t*)&g_a8l[base0 + nf * 8] =
            fp8x2((v0 - h0) * ACT_LO_SCALE, (v1 - h1) * ACT_LO_SCALE);
        *(uint32_t*)&g_ah[base1 + nf * 8] =
            packbf(__float2bfloat16(w0), __float2bfloat16(w1));
        *(uint16_t*)&g_a8h[base1 + nf * 8] = fp8x2(w0, w1);
        *(uint16_t*)&g_a8l[base1 + nf * 8] =
            fp8x2((w0 - g0) * ACT_LO_SCALE, (w1 - g1) * ACT_LO_SCALE);
    }
#undef LOADKV
}

// ---------------------------------------------------------------------------
// Launch
// ---------------------------------------------------------------------------
extern "C" void kernel_launch(void* const* d_in, const int* in_sizes, int n_in,
                              void* d_out, int out_size) {
    const float* x    = (const float*)d_in[0];
    const float* wq   = (const float*)d_in[1];
    const float* wk   = (const float*)d_in[2];
    const float* wv   = (const float*)d_in[3];
    const float* wo   = (const float*)d_in[4];
    const float* fcos = (const float*)d_in[5];
    const float* fsin = (const float*)d_in[6];
    float* out = (float*)d_out;

    float *qp, *kp, *vp;
    cudaGetSymbolAddress((void**)&qp, g_q);
    cudaGetSymbolAddress((void**)&kp, g_k);
    cudaGetSymbolAddress((void**)&vp, g_v);

    __nv_bfloat16 *xh, *wqh, *wkh, *wvh, *woh, *ah;
    uint8_t *x8h, *x8l, *wq8h, *wq8l, *wk8h, *wk8l, *wv8h, *wv8l, *wo8h, *wo8l;
    uint8_t *a8h, *a8l;
    cudaGetSymbolAddress((void**)&xh,   g_xh);
    cudaGetSymbolAddress((void**)&wqh,  g_wqh);
    cudaGetSymbolAddress((void**)&wkh,  g_wkh);
    cudaGetSymbolAddress((void**)&wvh,  g_wvh);
    cudaGetSymbolAddress((void**)&woh,  g_woh);
    cudaGetSymbolAddress((void**)&ah,   g_ah);
    cudaGetSymbolAddress((void**)&x8h,  g_x8h);
    cudaGetSymbolAddress((void**)&x8l,  g_x8l);
    cudaGetSymbolAddress((void**)&wq8h, g_wq8h);
    cudaGetSymbolAddress((void**)&wq8l, g_wq8l);
    cudaGetSymbolAddress((void**)&wk8h, g_wk8h);
    cudaGetSymbolAddress((void**)&wk8l, g_wk8l);
    cudaGetSymbolAddress((void**)&wv8h, g_wv8h);
    cudaGetSymbolAddress((void**)&wv8l, g_wv8l);
    cudaGetSymbolAddress((void**)&wo8h, g_wo8h);
    cudaGetSymbolAddress((void**)&wo8l, g_wo8l);
    cudaGetSymbolAddress((void**)&a8h,  g_a8h);
    cudaGetSymbolAddress((void**)&a8l,  g_a8l);

    cudaFuncSetAttribute(gemm_hx, cudaFuncAttributeMaxDynamicSharedMemorySize,
                         GEMM_SMEM);
    cudaFuncSetAttribute(flash_mma, cudaFuncAttributeMaxDynamicSharedMemorySize,
                         FLASH_SMEM);

    const int n4 = NELEM / 4;
    const int sblk = (n4 + 255) / 256;
    split_act<<<sblk, 256>>>(x,  xh,  x8h,  x8l,  n4);
    split_wgt<<<sblk, 256>>>(wq, wqh, wq8h, wq8l, n4);
    split_wgt<<<sblk, 256>>>(wk, wkh, wk8h, wk8l, n4);
    split_wgt<<<sblk, 256>>>(wv, wvh, wv8h, wv8l, n4);
    split_wgt<<<sblk, 256>>>(wo, woh, wo8h, wo8l, n4);

    dim3 ggrid(DIM / BN, MROWS / BM);   // (32, 32)
    gemm_hx<<<ggrid, 256, GEMM_SMEM>>>(xh, x8h, x8l, wqh, wq8l, wq8h, qp);
    gemm_hx<<<ggrid, 256, GEMM_SMEM>>>(xh, x8h, x8l, wkh, wk8l, wk8h, kp);
    gemm_hx<<<ggrid, 256, GEMM_SMEM>>>(xh, x8h, x8l, wvh, wv8l, wv8h, vp);

    rope_split_kernel<<<(BATCH * SEQ * NHEAD * 64) / 256, 256>>>(fcos, fsin);

    flash_mma<<<dim3(SEQ / 128, NHEAD, BATCH), 256, FLASH_SMEM>>>();

    gemm_hx<<<ggrid, 256, GEMM_SMEM>>>(ah, a8h, a8l, woh, wo8l, wo8h, out);
}

// round 8
// speedup vs baseline: 1.0005x; 1.0005x over previous
#include <cuda_runtime.h>
#include <cuda_bf16.h>
#include <cuda_fp16.h>
#include <math.h>
#include <stdint.h>

// Problem constants
#define BATCH 2
#define SEQ   2048
#define DIM   4096
#define NHEAD 32
#define HDIM  128
#define MROWS (BATCH * SEQ)   // 4096
#define NELEM (MROWS * DIM)   // 16777216

// fp32 scratch (QKV GEMM outputs / rope inputs)
__device__ float g_q[NELEM];
__device__ float g_k[NELEM];
__device__ float g_v[NELEM];
// bf16 hi arrays (hh pass, flash inputs)
__device__ __nv_bfloat16 g_xh[NELEM];
__device__ __nv_bfloat16 g_wqh[NELEM], g_wkh[NELEM], g_wvh[NELEM], g_woh[NELEM];
__device__ __nv_bfloat16 g_qh[NELEM], g_ql[NELEM];
__device__ __nv_bfloat16 g_kh[NELEM], g_kl[NELEM];
__device__ __nv_bfloat16 g_vh[NELEM], g_vl[NELEM];
__device__ __nv_bfloat16 g_ah[NELEM];
// fp16 cross-term arms
__device__ __half g_x16h[NELEM],  g_x16l[NELEM];
__device__ __half g_wq16l[NELEM], g_wq16h[NELEM];
__device__ __half g_wk16l[NELEM], g_wk16h[NELEM];
__device__ __half g_wv16l[NELEM], g_wv16h[NELEM];
__device__ __half g_wo16l[NELEM], g_wo16h[NELEM];
__device__ __half g_a16h[NELEM],  g_a16l[NELEM];

// Arm scales: act-lo x2^8, wgt-lo x2^12, wgt-hi x2^4  -> cross carries 2^12
#define ACT_LO_SCALE 256.0f
#define WGT_LO_SCALE 4096.0f
#define WGT_HI_SCALE 16.0f
#define CROSS_UNSCALE 0.000244140625f   // 2^-12

// ---------------------------------------------------------------------------
// Helpers
// ---------------------------------------------------------------------------
__device__ __forceinline__ uint32_t smem_u32(const void* p) {
    uint32_t a;
    asm("{ .reg .u64 t; cvta.to.shared.u64 t, %1; cvt.u32.u64 %0, t; }"
        : "=r"(a) : "l"(p));
    return a;
}

__device__ __forceinline__ void cpa16(uint32_t dst, const void* src) {
    asm volatile("cp.async.cg.shared.global [%0], [%1], 16;"
                 :: "r"(dst), "l"(src));
}
#define CP_COMMIT() asm volatile("cp.async.commit_group;" ::: "memory")
#define CP_WAIT(n)  asm volatile("cp.async.wait_group " #n ";" ::: "memory")

__device__ __forceinline__ void ldsm4(uint32_t addr, uint32_t& r0, uint32_t& r1,
                                      uint32_t& r2, uint32_t& r3) {
    asm volatile("ldmatrix.sync.aligned.m8n8.x4.shared.b16 {%0,%1,%2,%3}, [%4];"
                 : "=r"(r0), "=r"(r1), "=r"(r2), "=r"(r3) : "r"(addr));
}
__device__ __forceinline__ void ldsm4t(uint32_t addr, uint32_t& r0, uint32_t& r1,
                                       uint32_t& r2, uint32_t& r3) {
    asm volatile("ldmatrix.sync.aligned.m8n8.x4.trans.shared.b16 {%0,%1,%2,%3}, [%4];"
                 : "=r"(r0), "=r"(r1), "=r"(r2), "=r"(r3) : "r"(addr));
}

__device__ __forceinline__ void mma_bf16(float* c, const uint32_t* a,
                                         const uint32_t* b) {
    asm volatile(
        "mma.sync.aligned.m16n8k16.row.col.f32.bf16.bf16.f32 "
        "{%0,%1,%2,%3}, {%4,%5,%6,%7}, {%8,%9}, {%0,%1,%2,%3};"
        : "+f"(c[0]), "+f"(c[1]), "+f"(c[2]), "+f"(c[3])
        : "r"(a[0]), "r"(a[1]), "r"(a[2]), "r"(a[3]), "r"(b[0]), "r"(b[1]));
}
__device__ __forceinline__ void mma_bf16_2(float* c, const uint32_t* a,
                                           uint32_t b0, uint32_t b1) {
    asm volatile(
        "mma.sync.aligned.m16n8k16.row.col.f32.bf16.bf16.f32 "
        "{%0,%1,%2,%3}, {%4,%5,%6,%7}, {%8,%9}, {%0,%1,%2,%3};"
        : "+f"(c[0]), "+f"(c[1]), "+f"(c[2]), "+f"(c[3])
        : "r"(a[0]), "r"(a[1]), "r"(a[2]), "r"(a[3]), "r"(b0), "r"(b1));
}
// fp16 MMA with fp16 accumulators (the 2x-rate hypothesis)
__device__ __forceinline__ void mma_f16acc(uint32_t* c, const uint32_t* a,
                                           uint32_t b0, uint32_t b1) {
    asm volatile(
        "mma.sync.aligned.m16n8k16.row.col.f16.f16.f16.f16 "
        "{%0,%1}, {%2,%3,%4,%5}, {%6,%7}, {%0,%1};"
        : "+r"(c[0]), "+r"(c[1])
        : "r"(a[0]), "r"(a[1]), "r"(a[2]), "r"(a[3]), "r"(b0), "r"(b1));
}

__device__ __forceinline__ uint32_t packbf(__nv_bfloat16 a, __nv_bfloat16 b) {
    return ((uint32_t)__bfloat16_as_ushort(b) << 16) | __bfloat16_as_ushort(a);
}
__device__ __forceinline__ uint32_t packh(__half a, __half b) {
    return ((uint32_t)__half_as_ushort(b) << 16) | __half_as_ushort(a);
}
__device__ __forceinline__ void split2(float x, float y, uint32_t& hi, uint32_t& lo) {
    __nv_bfloat16 hx = __float2bfloat16(x);
    __nv_bfloat16 hy = __float2bfloat16(y);
    hi = packbf(hx, hy);
    lo = packbf(__float2bfloat16(x - __bfloat162float(hx)),
                __float2bfloat16(y - __bfloat162float(hy)));
}

// ---------------------------------------------------------------------------
// Split kernels
// ---------------------------------------------------------------------------
__global__ __launch_bounds__(256) void split_act(const float* __restrict__ src,
                                                 __nv_bfloat16* __restrict__ dh,
                                                 __half* __restrict__ d16h,
                                                 __half* __restrict__ d16l,
                                                 int n4) {
    int i = blockIdx.x * blockDim.x + threadIdx.x;
    if (i >= n4) return;
    float4 v = ((const float4*)src)[i];
    float hx = __bfloat162float(__float2bfloat16(v.x));
    float hy = __bfloat162float(__float2bfloat16(v.y));
    float hz = __bfloat162float(__float2bfloat16(v.z));
    float hw = __bfloat162float(__float2bfloat16(v.w));
    ((uint2*)dh)[i] = make_uint2(packbf(__float2bfloat16(v.x), __float2bfloat16(v.y)),
                                 packbf(__float2bfloat16(v.z), __float2bfloat16(v.w)));
    ((uint2*)d16h)[i] = make_uint2(packh(__float2half(hx), __float2half(hy)),
                                   packh(__float2half(hz), __float2half(hw)));
    ((uint2*)d16l)[i] = make_uint2(
        packh(__float2half((v.x - hx) * ACT_LO_SCALE),
              __float2half((v.y - hy) * ACT_LO_SCALE)),
        packh(__float2half((v.z - hz) * ACT_LO_SCALE),
              __float2half((v.w - hw) * ACT_LO_SCALE)));
}

__global__ __launch_bounds__(256) void split_wgt(const float* __restrict__ src,
                                                 __nv_bfloat16* __restrict__ dh,
                                                 __half* __restrict__ d16l,
                                                 __half* __restrict__ d16h,
                                                 int n4) {
    int i = blockIdx.x * blockDim.x + threadIdx.x;
    if (i >= n4) return;
    float4 v = ((const float4*)src)[i];
    float hx = __bfloat162float(__float2bfloat16(v.x));
    float hy = __bfloat162float(__float2bfloat16(v.y));
    float hz = __bfloat162float(__float2bfloat16(v.z));
    float hw = __bfloat162float(__float2bfloat16(v.w));
    ((uint2*)dh)[i] = make_uint2(packbf(__float2bfloat16(v.x), __float2bfloat16(v.y)),
                                 packbf(__float2bfloat16(v.z), __float2bfloat16(v.w)));
    ((uint2*)d16l)[i] = make_uint2(
        packh(__float2half((v.x - hx) * WGT_LO_SCALE),
              __float2half((v.y - hy) * WGT_LO_SCALE)),
        packh(__float2half((v.z - hz) * WGT_LO_SCALE),
              __float2half((v.w - hw) * WGT_LO_SCALE)));
    ((uint2*)d16h)[i] = make_uint2(
        packh(__float2half(hx * WGT_HI_SCALE), __float2half(hy * WGT_HI_SCALE)),
        packh(__float2half(hz * WGT_HI_SCALE), __float2half(hw * WGT_HI_SCALE)));
}

// ---------------------------------------------------------------------------
// GEMM v5 (NT): hh in bf16/f32acc; cross terms (xh*wl + xl*wh) in fp16/f16acc.
// 128x128 tile, BK=32, 8 warps (2x4, warp tile 64x32), 3-stage cp.async.
// ---------------------------------------------------------------------------
#define BM 128
#define BN 128
#define BK 32
#define NKC (DIM / BK)   // 128
#define PITCHB 80

#define OFF_AH  0
#define OFF_AXH 10240
#define OFF_AXL 20480
#define OFF_BH  30720
#define OFF_BXL 40960
#define OFF_BXH 51200
#define STAGE_BYTES 61440
#define GEMM_SMEM (3 * STAGE_BYTES)   // 184320

__global__ __launch_bounds__(256, 1)
void gemm_hx(const __nv_bfloat16* __restrict__ Ah,
             const __half* __restrict__ A16h, const __half* __restrict__ A16l,
             const __nv_bfloat16* __restrict__ Bh,
             const __half* __restrict__ B16l, const __half* __restrict__ B16h,
             float* __restrict__ C) {
    extern __shared__ char smem_raw[];
    const uint32_t sbase = smem_u32(smem_raw);
    const int tid  = threadIdx.x;
    const int wid  = tid >> 5;
    const int lane = tid & 31;
    const int wm   = wid >> 2;
    const int wn   = wid & 3;
    const int m0   = blockIdx.y * BM;
    const int n0   = blockIdx.x * BN;

    const char* Ahb  = (const char*)(Ah   + (size_t)m0 * DIM);
    const char* Axhb = (const char*)(A16h + (size_t)m0 * DIM);
    const char* Axlb = (const char*)(A16l + (size_t)m0 * DIM);
    const char* Bhb  = (const char*)(Bh   + (size_t)n0 * DIM);
    const char* Bxlb = (const char*)(B16l + (size_t)n0 * DIM);
    const char* Bxhb = (const char*)(B16h + (size_t)n0 * DIM);

    float accH[4][4][4];
    uint32_t accX[4][4][2];
#pragma unroll
    for (int i = 0; i < 4; i++)
#pragma unroll
        for (int j = 0; j < 4; j++) {
#pragma unroll
            for (int k = 0; k < 4; k++) accH[i][j][k] = 0.0f;
            accX[i][j][0] = 0u; accX[i][j][1] = 0u;
        }

    // 6 tiles x 512 segs of 16B; thread does seg tid and tid+256 of each tile
#define ISSUE(kc, stg)                                                        \
    {                                                                         \
        uint32_t sb = sbase + (uint32_t)(stg) * STAGE_BYTES;                  \
        _Pragma("unroll")                                                     \
        for (int u = 0; u < 2; u++) {                                         \
            int seg = tid + u * 256;                                          \
            int row = seg >> 2;                                               \
            int q   = seg & 3;                                                \
            uint32_t so = (uint32_t)row * PITCHB + q * 16;                    \
            size_t go = (size_t)row * (DIM * 2) + (size_t)(kc) * 64 + q * 16; \
            cpa16(sb + OFF_AH  + so, Ahb  + go);                              \
            cpa16(sb + OFF_AXH + so, Axhb + go);                              \
            cpa16(sb + OFF_AXL + so, Axlb + go);                              \
            cpa16(sb + OFF_BH  + so, Bhb  + go);                              \
            cpa16(sb + OFF_BXL + so, Bxlb + go);                              \
            cpa16(sb + OFF_BXH + so, Bxhb + go);                              \
        }                                                                     \
        CP_COMMIT();                                                          \
    }

    const uint32_t lm_off = (uint32_t)(lane & 15) * PITCHB + (lane >> 4) * 16;
    const uint32_t aAdr0 = (uint32_t)(wm * 64) * PITCHB + lm_off;
    const uint32_t bAdr0 = (uint32_t)(wn * 32) * PITCHB + lm_off;

    ISSUE(0, 0);
    ISSUE(1, 1);

    for (int kc = 0; kc < NKC; kc++) {
        CP_WAIT(1);
        __syncthreads();
        if (kc + 2 < NKC) { ISSUE(kc + 2, (kc + 2) % 3); }
        else { CP_COMMIT(); }

        const uint32_t stg = sbase + (uint32_t)(kc % 3) * STAGE_BYTES;

#pragma unroll
        for (int s = 0; s < 2; s++) {
            // ---- bf16 hh ----
            {
                uint32_t aF[4][4], bF[4][2];
#pragma unroll
                for (int mi = 0; mi < 4; mi++)
                    ldsm4(stg + OFF_AH + aAdr0 + mi * (16 * PITCHB) + s * 32,
                          aF[mi][0], aF[mi][1], aF[mi][2], aF[mi][3]);
#pragma unroll
                for (int nj = 0; nj < 2; nj++) {
                    uint32_t r0, r1, r2, r3;
                    ldsm4(stg + OFF_BH + bAdr0 + nj * (16 * PITCHB) + s * 32,
                          r0, r1, r2, r3);
                    bF[nj * 2][0] = r0; bF[nj * 2 + 1][0] = r1;
                    bF[nj * 2][1] = r2; bF[nj * 2 + 1][1] = r3;
                }
#pragma unroll
                for (int mi = 0; mi < 4; mi++)
#pragma unroll
                    for (int nf = 0; nf < 4; nf++)
                        mma_bf16(accH[mi][nf], aF[mi], bF[nf]);
            }
            // ---- fp16 cross: a16h*b16l ----
            {
                uint32_t aF[4][4], bF[4][2];
#pragma unroll
                for (int mi = 0; mi < 4; mi++)
                    ldsm4(stg + OFF_AXH + aAdr0 + mi * (16 * PITCHB) + s * 32,
                          aF[mi][0], aF[mi][1], aF[mi][2], aF[mi][3]);
#pragma unroll
                for (int nj = 0; nj < 2; nj++) {
                    uint32_t r0, r1, r2, r3;
                    ldsm4(stg + OFF_BXL + bAdr0 + nj * (16 * PITCHB) + s * 32,
                          r0, r1, r2, r3);
                    bF[nj * 2][0] = r0; bF[nj * 2 + 1][0] = r1;
                    bF[nj * 2][1] = r2; bF[nj * 2 + 1][1] = r3;
                }
#pragma unroll
                for (int mi = 0; mi < 4; mi++)
#pragma unroll
                    for (int nf = 0; nf < 4; nf++)
                        mma_f16acc(accX[mi][nf], aF[mi], bF[nf][0], bF[nf][1]);
            }
            // ---- fp16 cross: a16l*b16h ----
            {
                uint32_t aF[4][4], bF[4][2];
#pragma unroll
                for (int mi = 0; mi < 4; mi++)
                    ldsm4(stg + OFF_AXL + aAdr0 + mi * (16 * PITCHB) + s * 32,
                          aF[mi][0], aF[mi][1], aF[mi][2], aF[mi][3]);
#pragma unroll
                for (int nj = 0; nj < 2; nj++) {
                    uint32_t r0, r1, r2, r3;
                    ldsm4(stg + OFF_BXH + bAdr0 + nj * (16 * PITCHB) + s * 32,
                          r0, r1, r2, r3);
                    bF[nj * 2][0] = r0; bF[nj * 2 + 1][0] = r1;
                    bF[nj * 2][1] = r2; bF[nj * 2 + 1][1] = r3;
                }
#pragma unroll
                for (int mi = 0; mi < 4; mi++)
#pragma unroll
                    for (int nf = 0; nf < 4; nf++)
                        mma_f16acc(accX[mi][nf], aF[mi], bF[nf][0], bF[nf][1]);
            }
        }
        __syncthreads();
    }

#pragma unroll
    for (int mi = 0; mi < 4; mi++) {
#pragma unroll
        for (int nf = 0; nf < 4; nf++) {
            __half2 x01 = *(__half2*)&accX[mi][nf][0];
            __half2 x23 = *(__half2*)&accX[mi][nf][1];
            int row = m0 + wm * 64 + mi * 16 + (lane >> 2);
            int col = n0 + wn * 32 + nf * 8 + (lane & 3) * 2;
            *(float2*)&C[(size_t)row * DIM + col] = make_float2(
                accH[mi][nf][0] + __low2float(x01) * CROSS_UNSCALE,
                accH[mi][nf][1] + __high2float(x01) * CROSS_UNSCALE);
            *(float2*)&C[(size_t)(row + 8) * DIM + col] = make_float2(
                accH[mi][nf][2] + __low2float(x23) * CROSS_UNSCALE,
                accH[mi][nf][3] + __high2float(x23) * CROSS_UNSCALE);
        }
    }
#undef ISSUE
}

// ---------------------------------------------------------------------------
// RoPE + split (bf16 hi/lo for flash) — unchanged
// ---------------------------------------------------------------------------
__global__ __launch_bounds__(256) void rope_split_kernel(
    const float* __restrict__ fcos, const float* __restrict__ fsin) {
    int idx = blockIdx.x * blockDim.x + threadIdx.x;
    int j = idx & 63;
    int h = (idx >> 6) & 31;
    int s = (idx >> 11) & 2047;
    int b = idx >> 22;
    const float scale = 0.08838834764831845f;

    float c = fcos[s * 64 + j];
    float sn = fsin[s * 64 + j];
    size_t base = ((size_t)(b * SEQ + s)) * DIM + h * HDIM + 2 * j;

    float2 q2 = *(const float2*)&g_q[base];
    float2 k2 = *(const float2*)&g_k[base];
    float2 v2 = *(const float2*)&g_v[base];

    float qr = (q2.x * c - q2.y * sn) * scale;
    float qi = (q2.x * sn + q2.y * c) * scale;
    float kr = k2.x * c - k2.y * sn;
    float ki = k2.x * sn + k2.y * c;

    uint32_t hi, lo;
    split2(qr, qi, hi, lo);
    *(uint32_t*)&g_qh[base] = hi;
    *(uint32_t*)&g_ql[base] = lo;
    split2(kr, ki, hi, lo);
    *(uint32_t*)&g_kh[base] = hi;
    *(uint32_t*)&g_kl[base] = lo;
    split2(v2.x, v2.y, hi, lo);
    *(uint32_t*)&g_vh[base] = hi;
    *(uint32_t*)&g_vl[base] = lo;
}

// ---------------------------------------------------------------------------
// Flash attention (bf16x3, R5 core; epilogue emits bf16-hi + fp16 arms)
// ---------------------------------------------------------------------------
#define FPITCH 272
#define FQH 0
#define FQL (128 * FPITCH)
#define FSTG0 (2 * 128 * FPITCH)
#define FKH 0
#define FKL (64 * FPITCH)
#define FVH (128 * FPITCH)
#define FVL (192 * FPITCH)
#define FSTAGE (256 * FPITCH)
#define FLASH_SMEM (FSTG0 + 2 * FSTAGE)

__global__ __launch_bounds__(256)
void flash_mma() {
    extern __shared__ char smem_raw[];
    const uint32_t sbase = smem_u32(smem_raw);
    const int tid  = threadIdx.x;
    const int w    = tid >> 5;
    const int lane = tid & 31;
    const int qt = blockIdx.x;
    const int h  = blockIdx.y;
    const int b  = blockIdx.z;
    const int q0 = qt * 128;
    const size_t hoff = (size_t)h * HDIM;

    const char* khb = (const char*)g_kh;
    const char* klb = (const char*)g_kl;
    const char* vhb = (const char*)g_vh;
    const char* vlb = (const char*)g_vl;

    {
        const char* qhb = (const char*)g_qh;
        const char* qlb = (const char*)g_ql;
        for (int i = tid; i < 2048; i += 256) {
            int r = i >> 4, sg = (i & 15) * 16;
            size_t go = ((size_t)(b * SEQ + q0 + r) * DIM + hoff) * 2 + sg;
            uint32_t so = (uint32_t)r * FPITCH + sg;
            *(uint4*)(smem_raw + FQH + so) = *(const uint4*)(qhb + go);
            *(uint4*)(smem_raw + FQL + so) = *(const uint4*)(qlb + go);
        }
    }

#define LOADKV(t, stg)                                                        \
    {                                                                         \
        uint32_t sp = sbase + FSTG0 + (uint32_t)(stg) * FSTAGE;               \
        const int j0 = (t) * 64;                                              \
        _Pragma("unroll")                                                     \
        for (int u = 0; u < 4; u++) {                                         \
            int seg = tid + u * 256;                                          \
            int row = seg >> 4;                                               \
            int off = (seg & 15) * 16;                                        \
            uint32_t so = (uint32_t)row * FPITCH + off;                       \
            size_t go = ((size_t)(b * SEQ + j0 + row) * DIM + hoff) * 2 + off;\
            cpa16(sp + FKH + so, khb + go);                                   \
            cpa16(sp + FKL + so, klb + go);                                   \
            cpa16(sp + FVH + so, vhb + go);                                   \
            cpa16(sp + FVL + so, vlb + go);                                   \
        }                                                                     \
        CP_COMMIT();                                                          \
    }

    LOADKV(0, 0);

    float o[16][4];
#pragma unroll
    for (int nf = 0; nf < 16; nf++)
#pragma unroll
        for (int k = 0; k < 4; k++) o[nf][k] = 0.0f;
    float m0 = -INFINITY, m1 = -INFINITY, l0s = 0.0f, l1s = 0.0f;

    const uint32_t lmA = (uint32_t)(lane & 15) * FPITCH + (lane >> 4) * 16;
    const uint32_t qAdr = sbase + (uint32_t)(w * 16) * FPITCH + lmA;
    const uint32_t lmV = (uint32_t)(((lane >> 3) & 1) * 8 + (lane & 7)) * FPITCH
                         + (lane >> 4) * 16;

    for (int t = 0; t < 32; t++) {
        const int cur = t & 1;
        CP_WAIT(0);
        __syncthreads();
        if (t + 1 < 32) { LOADKV(t + 1, 1 - cur); }

        const uint32_t stg = sbase + FSTG0 + (uint32_t)cur * FSTAGE;

        float sc[8][4];
#pragma unroll
        for (int nf = 0; nf < 8; nf++)
#pragma unroll
            for (int k = 0; k < 4; k++) sc[nf][k] = 0.0f;

#pragma unroll
        for (int ks = 0; ks < 8; ks++) {
            uint32_t qh[4], ql[4];
            ldsm4(qAdr + FQH + ks * 32, qh[0], qh[1], qh[2], qh[3]);
            ldsm4(qAdr + FQL + ks * 32, ql[0], ql[1], ql[2], ql[3]);
#pragma unroll
            for (int nfp = 0; nfp < 4; nfp++) {
                uint32_t kAdr = stg + (uint32_t)(nfp * 16) * FPITCH + lmA + ks * 32;
                uint32_t kh0, kh1, kh2, kh3, kl0, kl1, kl2, kl3;
                ldsm4(kAdr + FKH, kh0, kh1, kh2, kh3);
                ldsm4(kAdr + FKL, kl0, kl1, kl2, kl3);
                mma_bf16_2(sc[nfp * 2],     qh, kh0, kh2);
                mma_bf16_2(sc[nfp * 2 + 1], qh, kh1, kh3);
                mma_bf16_2(sc[nfp * 2],     qh, kl0, kl2);
                mma_bf16_2(sc[nfp * 2 + 1], qh, kl1, kl3);
                mma_bf16_2(sc[nfp * 2],     ql, kh0, kh2);
                mma_bf16_2(sc[nfp * 2 + 1], ql, kh1, kh3);
            }
        }

        float mx0 = -INFINITY, mx1 = -INFINITY;
#pragma unroll
        for (int nf = 0; nf < 8; nf++) {
            mx0 = fmaxf(mx0, fmaxf(sc[nf][0], sc[nf][1]));
            mx1 = fmaxf(mx1, fmaxf(sc[nf][2], sc[nf][3]));
        }
        mx0 = fmaxf(mx0, __shfl_xor_sync(0xffffffffu, mx0, 1));
        mx0 = fmaxf(mx0, __shfl_xor_sync(0xffffffffu, mx0, 2));
        mx1 = fmaxf(mx1, __shfl_xor_sync(0xffffffffu, mx1, 1));
        mx1 = fmaxf(mx1, __shfl_xor_sync(0xffffffffu, mx1, 2));

        float mn0 = fmaxf(m0, mx0), mn1 = fmaxf(m1, mx1);
        float a0 = __expf(m0 - mn0), a1 = __expf(m1 - mn1);
        float rs0 = 0.0f, rs1 = 0.0f;
#pragma unroll
        for (int nf = 0; nf < 8; nf++) {
            sc[nf][0] = __expf(sc[nf][0] - mn0);
            sc[nf][1] = __expf(sc[nf][1] - mn0);
            sc[nf][2] = __expf(sc[nf][2] - mn1);
            sc[nf][3] = __expf(sc[nf][3] - mn1);
            rs0 += sc[nf][0] + sc[nf][1];
            rs1 += sc[nf][2] + sc[nf][3];
        }
        rs0 += __shfl_xor_sync(0xffffffffu, rs0, 1);
        rs0 += __shfl_xor_sync(0xffffffffu, rs0, 2);
        rs1 += __shfl_xor_sync(0xffffffffu, rs1, 1);
        rs1 += __shfl_xor_sync(0xffffffffu, rs1, 2);
        l0s = l0s * a0 + rs0;
        l1s = l1s * a1 + rs1;
        m0 = mn0; m1 = mn1;
#pragma unroll
        for (int nf = 0; nf < 16; nf++) {
            o[nf][0] *= a0; o[nf][1] *= a0;
            o[nf][2] *= a1; o[nf][3] *= a1;
        }

        uint32_t ph[4][4], pl[4][4];
#pragma unroll
        for (int ks = 0; ks < 4; ks++) {
            split2(sc[2 * ks][0],     sc[2 * ks][1],     ph[ks][0], pl[ks][0]);
            split2(sc[2 * ks][2],     sc[2 * ks][3],     ph[ks][1], pl[ks][1]);
            split2(sc[2 * ks + 1][0], sc[2 * ks + 1][1], ph[ks][2], pl[ks][2]);
            split2(sc[2 * ks + 1][2], sc[2 * ks + 1][3], ph[ks][3], pl[ks][3]);
        }

#pragma unroll
        for (int nfp = 0; nfp < 8; nfp++) {
#pragma unroll
            for (int ks = 0; ks < 4; ks++) {
                uint32_t vAdr = stg + (uint32_t)(ks * 16) * FPITCH + lmV + nfp * 32;
                uint32_t vh0, vh1, vh2, vh3, vl0, vl1, vl2, vl3;
                ldsm4t(vAdr + FVH, vh0, vh1, vh2, vh3);
                ldsm4t(vAdr + FVL, vl0, vl1, vl2, vl3);
                mma_bf16_2(o[nfp * 2],     ph[ks], vh0, vh1);
                mma_bf16_2(o[nfp * 2 + 1], ph[ks], vh2, vh3);
                mma_bf16_2(o[nfp * 2],     ph[ks], vl0, vl1);
                mma_bf16_2(o[nfp * 2 + 1], ph[ks], vl2, vl3);
                mma_bf16_2(o[nfp * 2],     pl[ks], vh0, vh1);
                mma_bf16_2(o[nfp * 2 + 1], pl[ks], vh2, vh3);
            }
        }
        __syncthreads();
    }

    // ---- normalize + emit bf16-hi + fp16 arms (feeds O-GEMM) ----
    const float inv0 = 1.0f / l0s;
    const float inv1 = 1.0f / l1s;
    const int g = lane >> 2;
    const int tq = lane & 3;
    const int row0 = q0 + w * 16 + g;
    size_t base0 = ((size_t)(b * SEQ + row0)) * DIM + hoff + tq * 2;
    size_t base1 = base0 + (size_t)8 * DIM;
#pragma unroll
    for (int nf = 0; nf < 16; nf++) {
        float v0 = o[nf][0] * inv0, v1 = o[nf][1] * inv0;
        float w0 = o[nf][2] * inv1, w1 = o[nf][3] * inv1;
        float h0 = __bfloat162float(__float2bfloat16(v0));
        float h1 = __bfloat162float(__float2bfloat16(v1));
        float g0 = __bfloat162float(__float2bfloat16(w0));
        float g1 = __bfloat162float(__float2bfloat16(w1));
        *(uint32_t*)&g_ah[base0 + nf * 8] =
            packbf(__float2bfloat16(v0), __float2bfloat16(v1));
        *(uint32_t*)&g_a16h[base0 + nf * 8] =
            packh(__float2half(h0), __float2half(h1));
        *(uint32_t*)&g_a16l[base0 + nf * 8] =
            packh(__float2half((v0 - h0) * ACT_LO_SCALE),
                  __float2half((v1 - h1) * ACT_LO_SCALE));
        *(uint32_t*)&g_ah[base1 + nf * 8] =
            packbf(__float2bfloat16(w0), __float2bfloat16(w1));
        *(uint32_t*)&g_a16h[base1 + nf * 8] =
            packh(__float2half(g0), __float2half(g1));
        *(uint32_t*)&g_a16l[base1 + nf * 8] =
            packh(__float2half((w0 - g0) * ACT_LO_SCALE),
                  __float2half((w1 - g1) * ACT_LO_SCALE));
    }
#undef LOADKV
}

// ---------------------------------------------------------------------------
// Launch
// ---------------------------------------------------------------------------
extern "C" void kernel_launch(void* const* d_in, const int* in_sizes, int n_in,
                              void* d_out, int out_size) {
    const float* x    = (const float*)d_in[0];
    const float* wq   = (const float*)d_in[1];
    const float* wk   = (const float*)d_in[2];
    const float* wv   = (const float*)d_in[3];
    const float* wo   = (const float*)d_in[4];
    const float* fcos = (const float*)d_in[5];
    const float* fsin = (const float*)d_in[6];
    float* out = (float*)d_out;

    float *qp, *kp, *vp;
    cudaGetSymbolAddress((void**)&qp, g_q);
    cudaGetSymbolAddress((void**)&kp, g_k);
    cudaGetSymbolAddress((void**)&vp, g_v);

    __nv_bfloat16 *xh, *wqh, *wkh, *wvh, *woh, *ah;
    __half *x16h, *x16l, *wq16l, *wq16h, *wk16l, *wk16h;
    __half *wv16l, *wv16h, *wo16l, *wo16h, *a16h, *a16l;
    cudaGetSymbolAddress((void**)&xh,    g_xh);
    cudaGetSymbolAddress((void**)&wqh,   g_wqh);
    cudaGetSymbolAddress((void**)&wkh,   g_wkh);
    cudaGetSymbolAddress((void**)&wvh,   g_wvh);
    cudaGetSymbolAddress((void**)&woh,   g_woh);
    cudaGetSymbolAddress((void**)&ah,    g_ah);
    cudaGetSymbolAddress((void**)&x16h,  g_x16h);
    cudaGetSymbolAddress((void**)&x16l,  g_x16l);
    cudaGetSymbolAddress((void**)&wq16l, g_wq16l);
    cudaGetSymbolAddress((void**)&wq16h, g_wq16h);
    cudaGetSymbolAddress((void**)&wk16l, g_wk16l);
    cudaGetSymbolAddress((void**)&wk16h, g_wk16h);
    cudaGetSymbolAddress((void**)&wv16l, g_wv16l);
    cudaGetSymbolAddress((void**)&wv16h, g_wv16h);
    cudaGetSymbolAddress((void**)&wo16l, g_wo16l);
    cudaGetSymbolAddress((void**)&wo16h, g_wo16h);
    cudaGetSymbolAddress((void**)&a16h,  g_a16h);
    cudaGetSymbolAddress((void**)&a16l,  g_a16l);

    cudaFuncSetAttribute(gemm_hx, cudaFuncAttributeMaxDynamicSharedMemorySize,
                         GEMM_SMEM);
    cudaFuncSetAttribute(flash_mma, cudaFuncAttributeMaxDynamicSharedMemorySize,
                         FLASH_SMEM);

    const int n4 = NELEM / 4;
    const int sblk = (n4 + 255) / 256;
    split_act<<<sblk, 256>>>(x,  xh,  x16h,  x16l,  n4);
    split_wgt<<<sblk, 256>>>(wq, wqh, wq16l, wq16h, n4);
    split_wgt<<<sblk, 256>>>(wk, wkh, wk16l, wk16h, n4);
    split_wgt<<<sblk, 256>>>(wv, wvh, wv16l, wv16h, n4);
    split_wgt<<<sblk, 256>>>(wo, woh, wo16l, wo16h, n4);

    dim3 ggrid(DIM / BN, MROWS / BM);   // (32, 32)
    gemm_hx<<<ggrid, 256, GEMM_SMEM>>>(xh, x16h, x16l, wqh, wq16l, wq16h, qp);
    gemm_hx<<<ggrid, 256, GEMM_SMEM>>>(xh, x16h, x16l, wkh, wk16l, wk16h, kp);
    gemm_hx<<<ggrid, 256, GEMM_SMEM>>>(xh, x16h, x16l, wvh, wv16l, wv16h, vp);

    rope_split_kernel<<<(BATCH * SEQ * NHEAD * 64) / 256, 256>>>(fcos, fsin);

    flash_mma<<<dim3(SEQ / 128, NHEAD, BATCH), 256, FLASH_SMEM>>>();

    gemm_hx<<<ggrid, 256, GEMM_SMEM>>>(ah, a16h, a16l, woh, wo16l, wo16h, out);
}

// round 9
// speedup vs baseline: 1.1019x; 1.1013x over previous
#include <cuda_runtime.h>
#include <cuda_bf16.h>
#include <math.h>
#include <stdint.h>

// Problem constants
#define BATCH 2
#define SEQ   2048
#define DIM   4096
#define NHEAD 32
#define HDIM  128
#define MROWS (BATCH * SEQ)   // 4096
#define NELEM (MROWS * DIM)   // 16777216

// pre-split bf16 scratch
__device__ __nv_bfloat16 g_xh[NELEM],  g_xl[NELEM];
__device__ __nv_bfloat16 g_wqh[NELEM], g_wql[NELEM];
__device__ __nv_bfloat16 g_wkh[NELEM], g_wkl[NELEM];
__device__ __nv_bfloat16 g_wvh[NELEM], g_wvl[NELEM];
__device__ __nv_bfloat16 g_woh[NELEM], g_wol[NELEM];
__device__ __nv_bfloat16 g_qh[NELEM],  g_ql[NELEM];
__device__ __nv_bfloat16 g_kh[NELEM],  g_kl[NELEM];
__device__ __nv_bfloat16 g_vh[NELEM],  g_vl[NELEM];
__device__ __nv_bfloat16 g_ah[NELEM],  g_al[NELEM];

// ---------------------------------------------------------------------------
// Helpers
// ---------------------------------------------------------------------------
__device__ __forceinline__ uint32_t smem_u32(const void* p) {
    uint32_t a;
    asm("{ .reg .u64 t; cvta.to.shared.u64 t, %1; cvt.u32.u64 %0, t; }"
        : "=r"(a) : "l"(p));
    return a;
}

__device__ __forceinline__ void cpa16(uint32_t dst, const void* src) {
    asm volatile("cp.async.cg.shared.global [%0], [%1], 16;"
                 :: "r"(dst), "l"(src));
}
#define CP_COMMIT() asm volatile("cp.async.commit_group;" ::: "memory")
#define CP_WAIT(n)  asm volatile("cp.async.wait_group " #n ";" ::: "memory")

__device__ __forceinline__ void ldsm4(uint32_t addr, uint32_t& r0, uint32_t& r1,
                                      uint32_t& r2, uint32_t& r3) {
    asm volatile("ldmatrix.sync.aligned.m8n8.x4.shared.b16 {%0,%1,%2,%3}, [%4];"
                 : "=r"(r0), "=r"(r1), "=r"(r2), "=r"(r3) : "r"(addr));
}
__device__ __forceinline__ void ldsm4t(uint32_t addr, uint32_t& r0, uint32_t& r1,
                                       uint32_t& r2, uint32_t& r3) {
    asm volatile("ldmatrix.sync.aligned.m8n8.x4.trans.shared.b16 {%0,%1,%2,%3}, [%4];"
                 : "=r"(r0), "=r"(r1), "=r"(r2), "=r"(r3) : "r"(addr));
}

__device__ __forceinline__ void mma_bf16(float* c, const uint32_t* a,
                                         const uint32_t* b) {
    asm volatile(
        "mma.sync.aligned.m16n8k16.row.col.f32.bf16.bf16.f32 "
        "{%0,%1,%2,%3}, {%4,%5,%6,%7}, {%8,%9}, {%0,%1,%2,%3};"
        : "+f"(c[0]), "+f"(c[1]), "+f"(c[2]), "+f"(c[3])
        : "r"(a[0]), "r"(a[1]), "r"(a[2]), "r"(a[3]), "r"(b[0]), "r"(b[1]));
}
__device__ __forceinline__ void mma_bf16_2(float* c, const uint32_t* a,
                                           uint32_t b0, uint32_t b1) {
    asm volatile(
        "mma.sync.aligned.m16n8k16.row.col.f32.bf16.bf16.f32 "
        "{%0,%1,%2,%3}, {%4,%5,%6,%7}, {%8,%9}, {%0,%1,%2,%3};"
        : "+f"(c[0]), "+f"(c[1]), "+f"(c[2]), "+f"(c[3])
        : "r"(a[0]), "r"(a[1]), "r"(a[2]), "r"(a[3]), "r"(b0), "r"(b1));
}

__device__ __forceinline__ uint32_t packbf(__nv_bfloat16 a, __nv_bfloat16 b) {
    return ((uint32_t)__bfloat16_as_ushort(b) << 16) | __bfloat16_as_ushort(a);
}
__device__ __forceinline__ void split2(float x, float y, uint32_t& hi, uint32_t& lo) {
    __nv_bfloat16 hx = __float2bfloat16(x);
    __nv_bfloat16 hy = __float2bfloat16(y);
    hi = packbf(hx, hy);
    lo = packbf(__float2bfloat16(x - __bfloat162float(hx)),
                __float2bfloat16(y - __bfloat162float(hy)));
}

// ---------------------------------------------------------------------------
// Split kernel: fp32 -> (hi, lo) bf16
// ---------------------------------------------------------------------------
__global__ __launch_bounds__(256) void split_kernel(const float* __restrict__ src,
                                                    __nv_bfloat16* __restrict__ dh,
                                                    __nv_bfloat16* __restrict__ dl,
                                                    int n4) {
    int i = blockIdx.x * blockDim.x + threadIdx.x;
    if (i >= n4) return;
    float4 v = ((const float4*)src)[i];
    uint32_t h0, l0, h1, l1;
    split2(v.x, v.y, h0, l0);
    split2(v.z, v.w, h1, l1);
    ((uint2*)dh)[i] = make_uint2(h0, h1);
    ((uint2*)dl)[i] = make_uint2(l0, l1);
}

// ---------------------------------------------------------------------------
// bf16x3 GEMM core (R5 mainloop): 128x128 tile, BK=32, 8 warps (2x4),
// 4-stage cp.async pipeline. Shared by QKV (rope epilogue) and O (fp32 out).
// ---------------------------------------------------------------------------
#define BM 128
#define BN 128
#define BK 32
#define NKC (DIM / BK)   // 128
#define PITCHB 80

#define OFF_AHI 0
#define OFF_ALO 10240
#define OFF_BHI 20480
#define OFF_BLO 30720
#define STAGE_BYTES 40960
#define GEMM_SMEM (4 * STAGE_BYTES)   // 163840

// Mainloop macro: computes acc[4][4][4] for tile (m0,n0) from (Ah,Al,Bh,Bl).
#define GEMM_MAINLOOP(Ahb, Alb, Bhb, Blb)                                     \
    const uint32_t lm_off = (uint32_t)(lane & 15) * PITCHB + (lane >> 4) * 16;\
    const uint32_t aAdr0 = (uint32_t)(wm * 64) * PITCHB + lm_off;             \
    const uint32_t bAdr0 = (uint32_t)(wn * 32) * PITCHB + lm_off;             \
    ISSUE(0, 0); ISSUE(1, 1); ISSUE(2, 2);                                    \
    for (int kc = 0; kc < NKC; kc++) {                                        \
        CP_WAIT(2);                                                           \
        __syncthreads();                                                      \
        if (kc + 3 < NKC) { ISSUE(kc + 3, (kc + 3) & 3); }                    \
        else { CP_COMMIT(); }                                                 \
        const uint32_t stg = sbase + (uint32_t)(kc & 3) * STAGE_BYTES;        \
        const uint32_t aHi = stg + OFF_AHI + aAdr0;                           \
        const uint32_t aLo = stg + OFF_ALO + aAdr0;                           \
        const uint32_t bHi = stg + OFF_BHI + bAdr0;                           \
        const uint32_t bLo = stg + OFF_BLO + bAdr0;                           \
        _Pragma("unroll")                                                     \
        for (int s = 0; s < 2; s++) {                                         \
            uint32_t aF[4][4], bH[4][2], bL[4][2];                            \
            _Pragma("unroll")                                                 \
            for (int mi = 0; mi < 4; mi++)                                    \
                ldsm4(aHi + mi * (16 * PITCHB) + s * 32,                      \
                      aF[mi][0], aF[mi][1], aF[mi][2], aF[mi][3]);            \
            _Pragma("unroll")                                                 \
            for (int nj = 0; nj < 2; nj++) {                                  \
                uint32_t r0, r1, r2, r3;                                      \
                ldsm4(bHi + nj * (16 * PITCHB) + s * 32, r0, r1, r2, r3);     \
                bH[nj * 2][0] = r0; bH[nj * 2 + 1][0] = r1;                   \
                bH[nj * 2][1] = r2; bH[nj * 2 + 1][1] = r3;                   \
                ldsm4(bLo + nj * (16 * PITCHB) + s * 32, r0, r1, r2, r3);     \
                bL[nj * 2][0] = r0; bL[nj * 2 + 1][0] = r1;                   \
                bL[nj * 2][1] = r2; bL[nj * 2 + 1][1] = r3;                   \
            }                                                                 \
            _Pragma("unroll")                                                 \
            for (int mi = 0; mi < 4; mi++)                                    \
                _Pragma("unroll")                                             \
                for (int nf = 0; nf < 4; nf++)                                \
                    mma_bf16(acc[mi][nf], aF[mi], bH[nf]);                    \
            _Pragma("unroll")                                                 \
            for (int mi = 0; mi < 4; mi++)                                    \
                _Pragma("unroll")                                             \
                for (int nf = 0; nf < 4; nf++)                                \
                    mma_bf16(acc[mi][nf], aF[mi], bL[nf]);                    \
            _Pragma("unroll")                                                 \
            for (int mi = 0; mi < 4; mi++)                                    \
                ldsm4(aLo + mi * (16 * PITCHB) + s * 32,                      \
                      aF[mi][0], aF[mi][1], aF[mi][2], aF[mi][3]);            \
            _Pragma("unroll")                                                 \
            for (int mi = 0; mi < 4; mi++)                                    \
                _Pragma("unroll")                                             \
                for (int nf = 0; nf < 4; nf++)                                \
                    mma_bf16(acc[mi][nf], aF[mi], bH[nf]);                    \
        }                                                                     \
        __syncthreads();                                                      \
    }

#define ISSUE(kc, stg)                                                        \
    {                                                                         \
        uint32_t sb = sbase + (uint32_t)(stg) * STAGE_BYTES;                  \
        size_t gk = (size_t)(kc) * 64;                                        \
        _Pragma("unroll")                                                     \
        for (int u = 0; u < 2; u++) {                                         \
            int seg = tid + u * 256;                                          \
            int row = seg >> 2;                                               \
            int off = (seg & 3) * 16;                                         \
            uint32_t so = (uint32_t)row * PITCHB + off;                       \
            size_t go = (size_t)row * (DIM * 2) + gk + off;                   \
            cpa16(sb + OFF_AHI + so, Ahb + go);                               \
            cpa16(sb + OFF_ALO + so, Alb + go);                               \
            cpa16(sb + OFF_BHI + so, Bhb + go);                               \
            cpa16(sb + OFF_BLO + so, Blb + go);                               \
        }                                                                     \
        CP_COMMIT();                                                          \
    }

// ---------------------------------------------------------------------------
// Fused QKV GEMM: grid.z selects {Q,K,V}. RoPE + scale applied in epilogue for
// Q/K; all outputs stored as pre-split bf16 hi/lo.
// ---------------------------------------------------------------------------
__global__ __launch_bounds__(256, 1)
void gemm_qkv(const __nv_bfloat16* __restrict__ Xh,
              const __nv_bfloat16* __restrict__ Xl,
              const float* __restrict__ fcos, const float* __restrict__ fsin) {
    extern __shared__ char smem_raw[];
    const uint32_t sbase = smem_u32(smem_raw);
    const int tid  = threadIdx.x;
    const int wid  = tid >> 5;
    const int lane = tid & 31;
    const int wm   = wid >> 2;
    const int wn   = wid & 3;
    const int m0   = blockIdx.y * BM;
    const int n0   = blockIdx.x * BN;
    const int z    = blockIdx.z;

    const __nv_bfloat16* Bh_p;
    const __nv_bfloat16* Bl_p;
    __nv_bfloat16* OH;
    __nv_bfloat16* OL;
    if (z == 0)      { Bh_p = g_wqh; Bl_p = g_wql; OH = g_qh; OL = g_ql; }
    else if (z == 1) { Bh_p = g_wkh; Bl_p = g_wkl; OH = g_kh; OL = g_kl; }
    else             { Bh_p = g_wvh; Bl_p = g_wvl; OH = g_vh; OL = g_vl; }

    const char* Ahb = (const char*)(Xh   + (size_t)m0 * DIM);
    const char* Alb = (const char*)(Xl   + (size_t)m0 * DIM);
    const char* Bhb = (const char*)(Bh_p + (size_t)n0 * DIM);
    const char* Blb = (const char*)(Bl_p + (size_t)n0 * DIM);

    float acc[4][4][4];
#pragma unroll
    for (int i = 0; i < 4; i++)
#pragma unroll
        for (int j = 0; j < 4; j++)
#pragma unroll
            for (int k = 0; k < 4; k++) acc[i][j][k] = 0.0f;

    GEMM_MAINLOOP(Ahb, Alb, Bhb, Blb)

    // Epilogue: RoPE (z<2) + q-scale (z==0) + bf16 split store
    const float qscale = 0.08838834764831845f;  // 1/sqrt(128)
#pragma unroll
    for (int mi = 0; mi < 4; mi++) {
#pragma unroll
        for (int nf = 0; nf < 4; nf++) {
            int row = m0 + wm * 64 + mi * 16 + (lane >> 2);
            int col = n0 + wn * 32 + nf * 8 + (lane & 3) * 2;
            float c0 = acc[mi][nf][0], c1 = acc[mi][nf][1];
            float c2 = acc[mi][nf][2], c3 = acc[mi][nf][3];
            if (z < 2) {
                int j = (col & 127) >> 1;
                int s0 = row & (SEQ - 1);
                int s1 = (row + 8) & (SEQ - 1);
                float cA = fcos[s0 * 64 + j], sA = fsin[s0 * 64 + j];
                float cB = fcos[s1 * 64 + j], sB = fsin[s1 * 64 + j];
                float r0 = c0 * cA - c1 * sA, i0 = c0 * sA + c1 * cA;
                float r1 = c2 * cB - c3 * sB, i1 = c2 * sB + c3 * cB;
                if (z == 0) { r0 *= qscale; i0 *= qscale; r1 *= qscale; i1 *= qscale; }
                c0 = r0; c1 = i0; c2 = r1; c3 = i1;
            }
            uint32_t hi, lo;
            split2(c0, c1, hi, lo);
            *(uint32_t*)&OH[(size_t)row * DIM + col] = hi;
            *(uint32_t*)&OL[(size_t)row * DIM + col] = lo;
            split2(c2, c3, hi, lo);
            *(uint32_t*)&OH[(size_t)(row + 8) * DIM + col] = hi;
            *(uint32_t*)&OL[(size_t)(row + 8) * DIM + col] = lo;
        }
    }
}

// ---------------------------------------------------------------------------
// O-projection GEMM: pre-split bf16 inputs, fp32 output (R5 gemm_bf16x3).
// ---------------------------------------------------------------------------
__global__ __launch_bounds__(256, 1)
void gemm_o(const __nv_bfloat16* __restrict__ Ah,
            const __nv_bfloat16* __restrict__ Al,
            const __nv_bfloat16* __restrict__ Bh,
            const __nv_bfloat16* __restrict__ Bl,
            float* __restrict__ C) {
    extern __shared__ char smem_raw[];
    const uint32_t sbase = smem_u32(smem_raw);
    const int tid  = threadIdx.x;
    const int wid  = tid >> 5;
    const int lane = tid & 31;
    const int wm   = wid >> 2;
    const int wn   = wid & 3;
    const int m0   = blockIdx.y * BM;
    const int n0   = blockIdx.x * BN;

    const char* Ahb = (const char*)(Ah + (size_t)m0 * DIM);
    const char* Alb = (const char*)(Al + (size_t)m0 * DIM);
    const char* Bhb = (const char*)(Bh + (size_t)n0 * DIM);
    const char* Blb = (const char*)(Bl + (size_t)n0 * DIM);

    float acc[4][4][4];
#pragma unroll
    for (int i = 0; i < 4; i++)
#pragma unroll
        for (int j = 0; j < 4; j++)
#pragma unroll
            for (int k = 0; k < 4; k++) acc[i][j][k] = 0.0f;

    GEMM_MAINLOOP(Ahb, Alb, Bhb, Blb)

#pragma unroll
    for (int mi = 0; mi < 4; mi++) {
#pragma unroll
        for (int nf = 0; nf < 4; nf++) {
            int row = m0 + wm * 64 + mi * 16 + (lane >> 2);
            int col = n0 + wn * 32 + nf * 8 + (lane & 3) * 2;
            *(float2*)&C[(size_t)row * DIM + col] =
                make_float2(acc[mi][nf][0], acc[mi][nf][1]);
            *(float2*)&C[(size_t)(row + 8) * DIM + col] =
                make_float2(acc[mi][nf][2], acc[mi][nf][3]);
        }
    }
}

// ---------------------------------------------------------------------------
// Flash attention (R5 exactly): pre-split bf16 inputs, cp.async KV pipeline,
// bf16x3 QK^T and PV, epilogue writes attn as bf16 hi/lo.
// ---------------------------------------------------------------------------
#define FPITCH 272
#define FQH 0
#define FQL (128 * FPITCH)
#define FSTG0 (2 * 128 * FPITCH)
#define FKH 0
#define FKL (64 * FPITCH)
#define FVH (128 * FPITCH)
#define FVL (192 * FPITCH)
#define FSTAGE (256 * FPITCH)
#define FLASH_SMEM (FSTG0 + 2 * FSTAGE)

__global__ __launch_bounds__(256)
void flash_mma() {
    extern __shared__ char smem_raw[];
    const uint32_t sbase = smem_u32(smem_raw);
    const int tid  = threadIdx.x;
    const int w    = tid >> 5;
    const int lane = tid & 31;
    const int qt = blockIdx.x;
    const int h  = blockIdx.y;
    const int b  = blockIdx.z;
    const int q0 = qt * 128;
    const size_t hoff = (size_t)h * HDIM;

    const char* khb = (const char*)g_kh;
    const char* klb = (const char*)g_kl;
    const char* vhb = (const char*)g_vh;
    const char* vlb = (const char*)g_vl;

    {
        const char* qhb = (const char*)g_qh;
        const char* qlb = (const char*)g_ql;
        for (int i = tid; i < 2048; i += 256) {
            int r = i >> 4, sg = (i & 15) * 16;
            size_t go = ((size_t)(b * SEQ + q0 + r) * DIM + hoff) * 2 + sg;
            uint32_t so = (uint32_t)r * FPITCH + sg;
            *(uint4*)(smem_raw + FQH + so) = *(const uint4*)(qhb + go);
            *(uint4*)(smem_raw + FQL + so) = *(const uint4*)(qlb + go);
        }
    }

#define LOADKV(t, stg)                                                        \
    {                                                                         \
        uint32_t sp = sbase + FSTG0 + (uint32_t)(stg) * FSTAGE;               \
        const int j0 = (t) * 64;                                              \
        _Pragma("unroll")                                                     \
        for (int u = 0; u < 4; u++) {                                         \
            int seg = tid + u * 256;                                          \
            int row = seg >> 4;                                               \
            int off = (seg & 15) * 16;                                        \
            uint32_t so = (uint32_t)row * FPITCH + off;                       \
            size_t go = ((size_t)(b * SEQ + j0 + row) * DIM + hoff) * 2 + off;\
            cpa16(sp + FKH + so, khb + go);                                   \
            cpa16(sp + FKL + so, klb + go);                                   \
            cpa16(sp + FVH + so, vhb + go);                                   \
            cpa16(sp + FVL + so, vlb + go);                                   \
        }                                                                     \
        CP_COMMIT();                                                          \
    }

    LOADKV(0, 0);

    float o[16][4];
#pragma unroll
    for (int nf = 0; nf < 16; nf++)
#pragma unroll
        for (int k = 0; k < 4; k++) o[nf][k] = 0.0f;
    float m0 = -INFINITY, m1 = -INFINITY, l0s = 0.0f, l1s = 0.0f;

    const uint32_t lmA = (uint32_t)(lane & 15) * FPITCH + (lane >> 4) * 16;
    const uint32_t qAdr = sbase + (uint32_t)(w * 16) * FPITCH + lmA;
    const uint32_t lmV = (uint32_t)(((lane >> 3) & 1) * 8 + (lane & 7)) * FPITCH
                         + (lane >> 4) * 16;

    for (int t = 0; t < 32; t++) {
        const int cur = t & 1;
        CP_WAIT(0);
        __syncthreads();
        if (t + 1 < 32) { LOADKV(t + 1, 1 - cur); }

        const uint32_t stg = sbase + FSTG0 + (uint32_t)cur * FSTAGE;

        float sc[8][4];
#pragma unroll
        for (int nf = 0; nf < 8; nf++)
#pragma unroll
            for (int k = 0; k < 4; k++) sc[nf][k] = 0.0f;

#pragma unroll
        for (int ks = 0; ks < 8; ks++) {
            uint32_t qh[4], ql[4];
            ldsm4(qAdr + FQH + ks * 32, qh[0], qh[1], qh[2], qh[3]);
            ldsm4(qAdr + FQL + ks * 32, ql[0], ql[1], ql[2], ql[3]);
#pragma unroll
            for (int nfp = 0; nfp < 4; nfp++) {
                uint32_t kAdr = stg + (uint32_t)(nfp * 16) * FPITCH + lmA + ks * 32;
                uint32_t kh0, kh1, kh2, kh3, kl0, kl1, kl2, kl3;
                ldsm4(kAdr + FKH, kh0, kh1, kh2, kh3);
                ldsm4(kAdr + FKL, kl0, kl1, kl2, kl3);
                mma_bf16_2(sc[nfp * 2],     qh, kh0, kh2);
                mma_bf16_2(sc[nfp * 2 + 1], qh, kh1, kh3);
                mma_bf16_2(sc[nfp * 2],     qh, kl0, kl2);
                mma_bf16_2(sc[nfp * 2 + 1], qh, kl1, kl3);
                mma_bf16_2(sc[nfp * 2],     ql, kh0, kh2);
                mma_bf16_2(sc[nfp * 2 + 1], ql, kh1, kh3);
            }
        }

        float mx0 = -INFINITY, mx1 = -INFINITY;
#pragma unroll
        for (int nf = 0; nf < 8; nf++) {
            mx0 = fmaxf(mx0, fmaxf(sc[nf][0], sc[nf][1]));
            mx1 = fmaxf(mx1, fmaxf(sc[nf][2], sc[nf][3]));
        }
        mx0 = fmaxf(mx0, __shfl_xor_sync(0xffffffffu, mx0, 1));
        mx0 = fmaxf(mx0, __shfl_xor_sync(0xffffffffu, mx0, 2));
        mx1 = fmaxf(mx1, __shfl_xor_sync(0xffffffffu, mx1, 1));
        mx1 = fmaxf(mx1, __shfl_xor_sync(0xffffffffu, mx1, 2));

        float mn0 = fmaxf(m0, mx0), mn1 = fmaxf(m1, mx1);
        float a0 = __expf(m0 - mn0), a1 = __expf(m1 - mn1);
        float rs0 = 0.0f, rs1 = 0.0f;
#pragma unroll
        for (int nf = 0; nf < 8; nf++) {
            sc[nf][0] = __expf(sc[nf][0] - mn0);
            sc[nf][1] = __expf(sc[nf][1] - mn0);
            sc[nf][2] = __expf(sc[nf][2] - mn1);
            sc[nf][3] = __expf(sc[nf][3] - mn1);
            rs0 += sc[nf][0] + sc[nf][1];
            rs1 += sc[nf][2] + sc[nf][3];
        }
        rs0 += __shfl_xor_sync(0xffffffffu, rs0, 1);
        rs0 += __shfl_xor_sync(0xffffffffu, rs0, 2);
        rs1 += __shfl_xor_sync(0xffffffffu, rs1, 1);
        rs1 += __shfl_xor_sync(0xffffffffu, rs1, 2);
        l0s = l0s * a0 + rs0;
        l1s = l1s * a1 + rs1;
        m0 = mn0; m1 = mn1;
#pragma unroll
        for (int nf = 0; nf < 16; nf++) {
            o[nf][0] *= a0; o[nf][1] *= a0;
            o[nf][2] *= a1; o[nf][3] *= a1;
        }

        uint32_t ph[4][4], pl[4][4];
#pragma unroll
        for (int ks = 0; ks < 4; ks++) {
            split2(sc[2 * ks][0],     sc[2 * ks][1],     ph[ks][0], pl[ks][0]);
            split2(sc[2 * ks][2],     sc[2 * ks][3],     ph[ks][1], pl[ks][1]);
            split2(sc[2 * ks + 1][0], sc[2 * ks + 1][1], ph[ks][2], pl[ks][2]);
            split2(sc[2 * ks + 1][2], sc[2 * ks + 1][3], ph[ks][3], pl[ks][3]);
        }

#pragma unroll
        for (int nfp = 0; nfp < 8; nfp++) {
#pragma unroll
            for (int ks = 0; ks < 4; ks++) {
                uint32_t vAdr = stg + (uint32_t)(ks * 16) * FPITCH + lmV + nfp * 32;
                uint32_t vh0, vh1, vh2, vh3, vl0, vl1, vl2, vl3;
                ldsm4t(vAdr + FVH, vh0, vh1, vh2, vh3);
                ldsm4t(vAdr + FVL, vl0, vl1, vl2, vl3);
                mma_bf16_2(o[nfp * 2],     ph[ks], vh0, vh1);
                mma_bf16_2(o[nfp * 2 + 1], ph[ks], vh2, vh3);
                mma_bf16_2(o[nfp * 2],     ph[ks], vl0, vl1);
                mma_bf16_2(o[nfp * 2 + 1], ph[ks], vl2, vl3);
                mma_bf16_2(o[nfp * 2],     pl[ks], vh0, vh1);
                mma_bf16_2(o[nfp * 2 + 1], pl[ks], vh2, vh3);
            }
        }
        __syncthreads();
    }

    const float inv0 = 1.0f / l0s;
    const float inv1 = 1.0f / l1s;
    const int g = lane >> 2;
    const int tq = lane & 3;
    const int row0 = q0 + w * 16 + g;
    size_t base0 = ((size_t)(b * SEQ + row0)) * DIM + hoff + tq * 2;
    size_t base1 = base0 + (size_t)8 * DIM;
#pragma unroll
    for (int nf = 0; nf < 16; nf++) {
        uint32_t hi, lo;
        split2(o[nf][0] * inv0, o[nf][1] * inv0, hi, lo);
        *(uint32_t*)&g_ah[base0 + nf * 8] = hi;
        *(uint32_t*)&g_al[base0 + nf * 8] = lo;
        split2(o[nf][2] * inv1, o[nf][3] * inv1, hi, lo);
        *(uint32_t*)&g_ah[base1 + nf * 8] = hi;
        *(uint32_t*)&g_al[base1 + nf * 8] = lo;
    }
#undef LOADKV
}

// ---------------------------------------------------------------------------
// Launch
// ---------------------------------------------------------------------------
extern "C" void kernel_launch(void* const* d_in, const int* in_sizes, int n_in,
                              void* d_out, int out_size) {
    const float* x    = (const float*)d_in[0];
    const float* wq   = (const float*)d_in[1];
    const float* wk   = (const float*)d_in[2];
    const float* wv   = (const float*)d_in[3];
    const float* wo   = (const float*)d_in[4];
    const float* fcos = (const float*)d_in[5];
    const float* fsin = (const float*)d_in[6];
    float* out = (float*)d_out;

    __nv_bfloat16 *xh, *xl, *wqh, *wql, *wkh, *wkl, *wvh, *wvl, *woh, *wol;
    __nv_bfloat16 *ah, *al;
    cudaGetSymbolAddress((void**)&xh,  g_xh);
    cudaGetSymbolAddress((void**)&xl,  g_xl);
    cudaGetSymbolAddress((void**)&wqh, g_wqh);
    cudaGetSymbolAddress((void**)&wql, g_wql);
    cudaGetSymbolAddress((void**)&wkh, g_wkh);
    cudaGetSymbolAddress((void**)&wkl, g_wkl);
    cudaGetSymbolAddress((void**)&wvh, g_wvh);
    cudaGetSymbolAddress((void**)&wvl, g_wvl);
    cudaGetSymbolAddress((void**)&woh, g_woh);
    cudaGetSymbolAddress((void**)&wol, g_wol);
    cudaGetSymbolAddress((void**)&ah,  g_ah);
    cudaGetSymbolAddress((void**)&al,  g_al);

    cudaFuncSetAttribute(gemm_qkv, cudaFuncAttributeMaxDynamicSharedMemorySize,
                         GEMM_SMEM);
    cudaFuncSetAttribute(gemm_o, cudaFuncAttributeMaxDynamicSharedMemorySize,
                         GEMM_SMEM);
    cudaFuncSetAttribute(flash_mma, cudaFuncAttributeMaxDynamicSharedMemorySize,
                         FLASH_SMEM);

    const int n4 = NELEM / 4;
    const int sblk = (n4 + 255) / 256;
    split_kernel<<<sblk, 256>>>(x,  xh,  xl,  n4);
    split_kernel<<<sblk, 256>>>(wq, wqh, wql, n4);
    split_kernel<<<sblk, 256>>>(wk, wkh, wkl, n4);
    split_kernel<<<sblk, 256>>>(wv, wvh, wvl, n4);
    split_kernel<<<sblk, 256>>>(wo, woh, wol, n4);

    gemm_qkv<<<dim3(DIM / BN, MROWS / BM, 3), 256, GEMM_SMEM>>>(xh, xl, fcos, fsin);

    flash_mma<<<dim3(SEQ / 128, NHEAD, BATCH), 256, FLASH_SMEM>>>();

    gemm_o<<<dim3(DIM / BN, MROWS / BM), 256, GEMM_SMEM>>>(ah, al, woh, wol, out);
}

// round 10
// speedup vs baseline: 1.1149x; 1.0117x over previous
#include <cuda_runtime.h>
#include <cuda_bf16.h>
#include <math.h>
#include <stdint.h>

// Problem constants
#define BATCH 2
#define SEQ   2048
#define DIM   4096
#define NHEAD 32
#define HDIM  128
#define MROWS (BATCH * SEQ)   // 4096
#define NELEM (MROWS * DIM)   // 16777216

// pre-split bf16 scratch
__device__ __nv_bfloat16 g_xh[NELEM],  g_xl[NELEM];
__device__ __nv_bfloat16 g_wqh[NELEM], g_wql[NELEM];
__device__ __nv_bfloat16 g_wkh[NELEM], g_wkl[NELEM];
__device__ __nv_bfloat16 g_wvh[NELEM], g_wvl[NELEM];
__device__ __nv_bfloat16 g_woh[NELEM], g_wol[NELEM];
__device__ __nv_bfloat16 g_qh[NELEM],  g_ql[NELEM];
__device__ __nv_bfloat16 g_kh[NELEM],  g_kl[NELEM];
__device__ __nv_bfloat16 g_vh[NELEM],  g_vl[NELEM];
__device__ __nv_bfloat16 g_ah[NELEM],  g_al[NELEM];

// ---------------------------------------------------------------------------
// Helpers
// ---------------------------------------------------------------------------
__device__ __forceinline__ uint32_t smem_u32(const void* p) {
    uint32_t a;
    asm("{ .reg .u64 t; cvta.to.shared.u64 t, %1; cvt.u32.u64 %0, t; }"
        : "=r"(a) : "l"(p));
    return a;
}

__device__ __forceinline__ void cpa16(uint32_t dst, const void* src) {
    asm volatile("cp.async.cg.shared.global [%0], [%1], 16;"
                 :: "r"(dst), "l"(src));
}
#define CP_COMMIT() asm volatile("cp.async.commit_group;" ::: "memory")
#define CP_WAIT(n)  asm volatile("cp.async.wait_group " #n ";" ::: "memory")

__device__ __forceinline__ void ldsm4(uint32_t addr, uint32_t& r0, uint32_t& r1,
                                      uint32_t& r2, uint32_t& r3) {
    asm volatile("ldmatrix.sync.aligned.m8n8.x4.shared.b16 {%0,%1,%2,%3}, [%4];"
                 : "=r"(r0), "=r"(r1), "=r"(r2), "=r"(r3) : "r"(addr));
}
__device__ __forceinline__ void ldsm4t(uint32_t addr, uint32_t& r0, uint32_t& r1,
                                       uint32_t& r2, uint32_t& r3) {
    asm volatile("ldmatrix.sync.aligned.m8n8.x4.trans.shared.b16 {%0,%1,%2,%3}, [%4];"
                 : "=r"(r0), "=r"(r1), "=r"(r2), "=r"(r3) : "r"(addr));
}

__device__ __forceinline__ void mma_bf16(float* c, const uint32_t* a,
                                         const uint32_t* b) {
    asm volatile(
        "mma.sync.aligned.m16n8k16.row.col.f32.bf16.bf16.f32 "
        "{%0,%1,%2,%3}, {%4,%5,%6,%7}, {%8,%9}, {%0,%1,%2,%3};"
        : "+f"(c[0]), "+f"(c[1]), "+f"(c[2]), "+f"(c[3])
        : "r"(a[0]), "r"(a[1]), "r"(a[2]), "r"(a[3]), "r"(b[0]), "r"(b[1]));
}
__device__ __forceinline__ void mma_bf16_2(float* c, const uint32_t* a,
                                           uint32_t b0, uint32_t b1) {
    asm volatile(
        "mma.sync.aligned.m16n8k16.row.col.f32.bf16.bf16.f32 "
        "{%0,%1,%2,%3}, {%4,%5,%6,%7}, {%8,%9}, {%0,%1,%2,%3};"
        : "+f"(c[0]), "+f"(c[1]), "+f"(c[2]), "+f"(c[3])
        : "r"(a[0]), "r"(a[1]), "r"(a[2]), "r"(a[3]), "r"(b0), "r"(b1));
}

__device__ __forceinline__ uint32_t packbf(__nv_bfloat16 a, __nv_bfloat16 b) {
    return ((uint32_t)__bfloat16_as_ushort(b) << 16) | __bfloat16_as_ushort(a);
}
__device__ __forceinline__ void split2(float x, float y, uint32_t& hi, uint32_t& lo) {
    __nv_bfloat16 hx = __float2bfloat16(x);
    __nv_bfloat16 hy = __float2bfloat16(y);
    hi = packbf(hx, hy);
    lo = packbf(__float2bfloat16(x - __bfloat162float(hx)),
                __float2bfloat16(y - __bfloat162float(hy)));
}

// ---------------------------------------------------------------------------
// Merged split kernel: one launch converts all 5 fp32 tensors to bf16 hi/lo.
// blockIdx.y selects the tensor.
// ---------------------------------------------------------------------------
__global__ __launch_bounds__(256) void split5_kernel(
    const float* __restrict__ s0, const float* __restrict__ s1,
    const float* __restrict__ s2, const float* __restrict__ s3,
    const float* __restrict__ s4) {
    int i = blockIdx.x * blockDim.x + threadIdx.x;   // < NELEM/4
    const float* src;
    __nv_bfloat16 *dh, *dl;
    switch (blockIdx.y) {
        case 0:  src = s0; dh = g_xh;  dl = g_xl;  break;
        case 1:  src = s1; dh = g_wqh; dl = g_wql; break;
        case 2:  src = s2; dh = g_wkh; dl = g_wkl; break;
        case 3:  src = s3; dh = g_wvh; dl = g_wvl; break;
        default: src = s4; dh = g_woh; dl = g_wol; break;
    }
    float4 v = ((const float4*)src)[i];
    uint32_t h0, l0, h1, l1;
    split2(v.x, v.y, h0, l0);
    split2(v.z, v.w, h1, l1);
    ((uint2*)dh)[i] = make_uint2(h0, h1);
    ((uint2*)dl)[i] = make_uint2(l0, l1);
}

// ---------------------------------------------------------------------------
// bf16x3 GEMM core: 128x128 tile, BK=32, 8 warps (2x4), 4-stage cp.async.
// ---------------------------------------------------------------------------
#define BM 128
#define BN 128
#define BK 32
#define NKC (DIM / BK)   // 128
#define PITCHB 80

#define OFF_AHI 0
#define OFF_ALO 10240
#define OFF_BHI 20480
#define OFF_BLO 30720
#define STAGE_BYTES 40960
#define GEMM_SMEM (4 * STAGE_BYTES)   // 163840

#define GEMM_MAINLOOP(Ahb, Alb, Bhb, Blb)                                     \
    const uint32_t lm_off = (uint32_t)(lane & 15) * PITCHB + (lane >> 4) * 16;\
    const uint32_t aAdr0 = (uint32_t)(wm * 64) * PITCHB + lm_off;             \
    const uint32_t bAdr0 = (uint32_t)(wn * 32) * PITCHB + lm_off;             \
    ISSUE(0, 0); ISSUE(1, 1); ISSUE(2, 2);                                    \
    for (int kc = 0; kc < NKC; kc++) {                                        \
        CP_WAIT(2);                                                           \
        __syncthreads();                                                      \
        if (kc + 3 < NKC) { ISSUE(kc + 3, (kc + 3) & 3); }                    \
        else { CP_COMMIT(); }                                                 \
        const uint32_t stg = sbase + (uint32_t)(kc & 3) * STAGE_BYTES;        \
        const uint32_t aHi = stg + OFF_AHI + aAdr0;                           \
        const uint32_t aLo = stg + OFF_ALO + aAdr0;                           \
        const uint32_t bHi = stg + OFF_BHI + bAdr0;                           \
        const uint32_t bLo = stg + OFF_BLO + bAdr0;                           \
        _Pragma("unroll")                                                     \
        for (int s = 0; s < 2; s++) {                                         \
            uint32_t aF[4][4], bH[4][2], bL[4][2];                            \
            _Pragma("unroll")                                                 \
            for (int mi = 0; mi < 4; mi++)                                    \
                ldsm4(aHi + mi * (16 * PITCHB) + s * 32,                      \
                      aF[mi][0], aF[mi][1], aF[mi][2], aF[mi][3]);            \
            _Pragma("unroll")                                                 \
            for (int nj = 0; nj < 2; nj++) {                                  \
                uint32_t r0, r1, r2, r3;                                      \
                ldsm4(bHi + nj * (16 * PITCHB) + s * 32, r0, r1, r2, r3);     \
                bH[nj * 2][0] = r0; bH[nj * 2 + 1][0] = r1;                   \
                bH[nj * 2][1] = r2; bH[nj * 2 + 1][1] = r3;                   \
                ldsm4(bLo + nj * (16 * PITCHB) + s * 32, r0, r1, r2, r3);     \
                bL[nj * 2][0] = r0; bL[nj * 2 + 1][0] = r1;                   \
                bL[nj * 2][1] = r2; bL[nj * 2 + 1][1] = r3;                   \
            }                                                                 \
            _Pragma("unroll")                                                 \
            for (int mi = 0; mi < 4; mi++)                                    \
                _Pragma("unroll")                                             \
                for (int nf = 0; nf < 4; nf++)                                \
                    mma_bf16(acc[mi][nf], aF[mi], bH[nf]);                    \
            _Pragma("unroll")                                                 \
            for (int mi = 0; mi < 4; mi++)                                    \
                _Pragma("unroll")                                             \
                for (int nf = 0; nf < 4; nf++)                                \
                    mma_bf16(acc[mi][nf], aF[mi], bL[nf]);                    \
            _Pragma("unroll")                                                 \
            for (int mi = 0; mi < 4; mi++)                                    \
                ldsm4(aLo + mi * (16 * PITCHB) + s * 32,                      \
                      aF[mi][0], aF[mi][1], aF[mi][2], aF[mi][3]);            \
            _Pragma("unroll")                                                 \
            for (int mi = 0; mi < 4; mi++)                                    \
                _Pragma("unroll")                                             \
                for (int nf = 0; nf < 4; nf++)                                \
                    mma_bf16(acc[mi][nf], aF[mi], bH[nf]);                    \
        }                                                                     \
        __syncthreads();                                                      \
    }

#define ISSUE(kc, stg)                                                        \
    {                                                                         \
        uint32_t sb = sbase + (uint32_t)(stg) * STAGE_BYTES;                  \
        size_t gk = (size_t)(kc) * 64;                                        \
        _Pragma("unroll")                                                     \
        for (int u = 0; u < 2; u++) {                                         \
            int seg = tid + u * 256;                                          \
            int row = seg >> 2;                                               \
            int off = (seg & 3) * 16;                                         \
            uint32_t so = (uint32_t)row * PITCHB + off;                       \
            size_t go = (size_t)row * (DIM * 2) + gk + off;                   \
            cpa16(sb + OFF_AHI + so, Ahb + go);                               \
            cpa16(sb + OFF_ALO + so, Alb + go);                               \
            cpa16(sb + OFF_BHI + so, Bhb + go);                               \
            cpa16(sb + OFF_BLO + so, Blb + go);                               \
        }                                                                     \
        CP_COMMIT();                                                          \
    }

// ---------------------------------------------------------------------------
// QKV GEMM (one launch per z in {0=Q,1=K,2=V}). RoPE+scale fused in epilogue
// using smem-staged trig (reuses the dead pipeline stages after the mainloop).
// Output stored pre-split bf16 hi/lo.
// ---------------------------------------------------------------------------
#define TRIG_PITCH 66   // float2 per row (128 rows x 66 x 8B = 67.6 KB)

__global__ __launch_bounds__(256, 1)
void gemm_qkv(const __nv_bfloat16* __restrict__ Xh,
              const __nv_bfloat16* __restrict__ Xl,
              const __nv_bfloat16* __restrict__ Wh,
              const __nv_bfloat16* __restrict__ Wl,
              __nv_bfloat16* __restrict__ OH,
              __nv_bfloat16* __restrict__ OL,
              const float* __restrict__ fcos, const float* __restrict__ fsin,
              int z) {
    extern __shared__ char smem_raw[];
    const uint32_t sbase = smem_u32(smem_raw);
    const int tid  = threadIdx.x;
    const int wid  = tid >> 5;
    const int lane = tid & 31;
    const int wm   = wid >> 2;
    const int wn   = wid & 3;
    const int m0   = blockIdx.y * BM;
    const int n0   = blockIdx.x * BN;

    const char* Ahb = (const char*)(Xh + (size_t)m0 * DIM);
    const char* Alb = (const char*)(Xl + (size_t)m0 * DIM);
    const char* Bhb = (const char*)(Wh + (size_t)n0 * DIM);
    const char* Blb = (const char*)(Wl + (size_t)n0 * DIM);

    float acc[4][4][4];
#pragma unroll
    for (int i = 0; i < 4; i++)
#pragma unroll
        for (int j = 0; j < 4; j++)
#pragma unroll
            for (int k = 0; k < 4; k++) acc[i][j][k] = 0.0f;

    GEMM_MAINLOOP(Ahb, Alb, Bhb, Blb)

    // ---- Stage trig table into (now dead) pipeline smem ----
    float2* trig = (float2*)smem_raw;
    if (z < 2) {
        for (int i = tid; i < 128 * 64; i += 256) {
            int sl = i >> 6, j = i & 63;
            int s = (m0 + sl) & (SEQ - 1);
            trig[sl * TRIG_PITCH + j] = make_float2(fcos[s * 64 + j],
                                                    fsin[s * 64 + j]);
        }
        __syncthreads();
    }

    const float qscale = 0.08838834764831845f;  // 1/sqrt(128)
#pragma unroll
    for (int mi = 0; mi < 4; mi++) {
#pragma unroll
        for (int nf = 0; nf < 4; nf++) {
            int rl  = wm * 64 + mi * 16 + (lane >> 2);    // row_local
            int row = m0 + rl;
            int col = n0 + wn * 32 + nf * 8 + (lane & 3) * 2;
            float c0 = acc[mi][nf][0], c1 = acc[mi][nf][1];
            float c2 = acc[mi][nf][2], c3 = acc[mi][nf][3];
            if (z < 2) {
                int j = (wn * 32 + nf * 8) / 2 + (lane & 3);  // (col&127)>>1
                float2 tA = trig[rl * TRIG_PITCH + j];
                float2 tB = trig[(rl + 8) * TRIG_PITCH + j];
                float r0 = c0 * tA.x - c1 * tA.y, i0 = c0 * tA.y + c1 * tA.x;
                float r1 = c2 * tB.x - c3 * tB.y, i1 = c2 * tB.y + c3 * tB.x;
                if (z == 0) { r0 *= qscale; i0 *= qscale; r1 *= qscale; i1 *= qscale; }
                c0 = r0; c1 = i0; c2 = r1; c3 = i1;
            }
            uint32_t hi, lo;
            split2(c0, c1, hi, lo);
            *(uint32_t*)&OH[(size_t)row * DIM + col] = hi;
            *(uint32_t*)&OL[(size_t)row * DIM + col] = lo;
            split2(c2, c3, hi, lo);
            *(uint32_t*)&OH[(size_t)(row + 8) * DIM + col] = hi;
            *(uint32_t*)&OL[(size_t)(row + 8) * DIM + col] = lo;
        }
    }
}

// ---------------------------------------------------------------------------
// O-projection GEMM: pre-split bf16 inputs, fp32 output.
// ---------------------------------------------------------------------------
__global__ __launch_bounds__(256, 1)
void gemm_o(const __nv_bfloat16* __restrict__ Ah,
            const __nv_bfloat16* __restrict__ Al,
            const __nv_bfloat16* __restrict__ Bh,
            const __nv_bfloat16* __restrict__ Bl,
            float* __restrict__ C) {
    extern __shared__ char smem_raw[];
    const uint32_t sbase = smem_u32(smem_raw);
    const int tid  = threadIdx.x;
    const int wid  = tid >> 5;
    const int lane = tid & 31;
    const int wm   = wid >> 2;
    const int wn   = wid & 3;
    const int m0   = blockIdx.y * BM;
    const int n0   = blockIdx.x * BN;

    const char* Ahb = (const char*)(Ah + (size_t)m0 * DIM);
    const char* Alb = (const char*)(Al + (size_t)m0 * DIM);
    const char* Bhb = (const char*)(Bh + (size_t)n0 * DIM);
    const char* Blb = (const char*)(Bl + (size_t)n0 * DIM);

    float acc[4][4][4];
#pragma unroll
    for (int i = 0; i < 4; i++)
#pragma unroll
        for (int j = 0; j < 4; j++)
#pragma unroll
            for (int k = 0; k < 4; k++) acc[i][j][k] = 0.0f;

    GEMM_MAINLOOP(Ahb, Alb, Bhb, Blb)

#pragma unroll
    for (int mi = 0; mi < 4; mi++) {
#pragma unroll
        for (int nf = 0; nf < 4; nf++) {
            int row = m0 + wm * 64 + mi * 16 + (lane >> 2);
            int col = n0 + wn * 32 + nf * 8 + (lane & 3) * 2;
            *(float2*)&C[(size_t)row * DIM + col] =
                make_float2(acc[mi][nf][0], acc[mi][nf][1]);
            *(float2*)&C[(size_t)(row + 8) * DIM + col] =
                make_float2(acc[mi][nf][2], acc[mi][nf][3]);
        }
    }
}

// ---------------------------------------------------------------------------
// Flash attention (R5 exactly)
// ---------------------------------------------------------------------------
#define FPITCH 272
#define FQH 0
#define FQL (128 * FPITCH)
#define FSTG0 (2 * 128 * FPITCH)
#define FKH 0
#define FKL (64 * FPITCH)
#define FVH (128 * FPITCH)
#define FVL (192 * FPITCH)
#define FSTAGE (256 * FPITCH)
#define FLASH_SMEM (FSTG0 + 2 * FSTAGE)

__global__ __launch_bounds__(256)
void flash_mma() {
    extern __shared__ char smem_raw[];
    const uint32_t sbase = smem_u32(smem_raw);
    const int tid  = threadIdx.x;
    const int w    = tid >> 5;
    const int lane = tid & 31;
    const int qt = blockIdx.x;
    const int h  = blockIdx.y;
    const int b  = blockIdx.z;
    const int q0 = qt * 128;
    const size_t hoff = (size_t)h * HDIM;

    const char* khb = (const char*)g_kh;
    const char* klb = (const char*)g_kl;
    const char* vhb = (const char*)g_vh;
    const char* vlb = (const char*)g_vl;

    {
        const char* qhb = (const char*)g_qh;
        const char* qlb = (const char*)g_ql;
        for (int i = tid; i < 2048; i += 256) {
            int r = i >> 4, sg = (i & 15) * 16;
            size_t go = ((size_t)(b * SEQ + q0 + r) * DIM + hoff) * 2 + sg;
            uint32_t so = (uint32_t)r * FPITCH + sg;
            *(uint4*)(smem_raw + FQH + so) = *(const uint4*)(qhb + go);
            *(uint4*)(smem_raw + FQL + so) = *(const uint4*)(qlb + go);
        }
    }

#define LOADKV(t, stg)                                                        \
    {                                                                         \
        uint32_t sp = sbase + FSTG0 + (uint32_t)(stg) * FSTAGE;               \
        const int j0 = (t) * 64;                                              \
        _Pragma("unroll")                                                     \
        for (int u = 0; u < 4; u++) {                                         \
            int seg = tid + u * 256;                                          \
            int row = seg >> 4;                                               \
            int off = (seg & 15) * 16;                                        \
            uint32_t so = (uint32_t)row * FPITCH + off;                       \
            size_t go = ((size_t)(b * SEQ + j0 + row) * DIM + hoff) * 2 + off;\
            cpa16(sp + FKH + so, khb + go);                                   \
            cpa16(sp + FKL + so, klb + go);                                   \
            cpa16(sp + FVH + so, vhb + go);                                   \
            cpa16(sp + FVL + so, vlb + go);                                   \
        }                                                                     \
        CP_COMMIT();                                                          \
    }

    LOADKV(0, 0);

    float o[16][4];
#pragma unroll
    for (int nf = 0; nf < 16; nf++)
#pragma unroll
        for (int k = 0; k < 4; k++) o[nf][k] = 0.0f;
    float m0 = -INFINITY, m1 = -INFINITY, l0s = 0.0f, l1s = 0.0f;

    const uint32_t lmA = (uint32_t)(lane & 15) * FPITCH + (lane >> 4) * 16;
    const uint32_t qAdr = sbase + (uint32_t)(w * 16) * FPITCH + lmA;
    const uint32_t lmV = (uint32_t)(((lane >> 3) & 1) * 8 + (lane & 7)) * FPITCH
                         + (lane >> 4) * 16;

    for (int t = 0; t < 32; t++) {
        const int cur = t & 1;
        CP_WAIT(0);
        __syncthreads();
        if (t + 1 < 32) { LOADKV(t + 1, 1 - cur); }

        const uint32_t stg = sbase + FSTG0 + (uint32_t)cur * FSTAGE;

        float sc[8][4];
#pragma unroll
        for (int nf = 0; nf < 8; nf++)
#pragma unroll
            for (int k = 0; k < 4; k++) sc[nf][k] = 0.0f;

#pragma unroll
        for (int ks = 0; ks < 8; ks++) {
            uint32_t qh[4], ql[4];
            ldsm4(qAdr + FQH + ks * 32, qh[0], qh[1], qh[2], qh[3]);
            ldsm4(qAdr + FQL + ks * 32, ql[0], ql[1], ql[2], ql[3]);
#pragma unroll
            for (int nfp = 0; nfp < 4; nfp++) {
                uint32_t kAdr = stg + (uint32_t)(nfp * 16) * FPITCH + lmA + ks * 32;
                uint32_t kh0, kh1, kh2, kh3, kl0, kl1, kl2, kl3;
                ldsm4(kAdr + FKH, kh0, kh1, kh2, kh3);
                ldsm4(kAdr + FKL, kl0, kl1, kl2, kl3);
                mma_bf16_2(sc[nfp * 2],     qh, kh0, kh2);
                mma_bf16_2(sc[nfp * 2 + 1], qh, kh1, kh3);
                mma_bf16_2(sc[nfp * 2],     qh, kl0, kl2);
                mma_bf16_2(sc[nfp * 2 + 1], qh, kl1, kl3);
                mma_bf16_2(sc[nfp * 2],     ql, kh0, kh2);
                mma_bf16_2(sc[nfp * 2 + 1], ql, kh1, kh3);
            }
        }

        float mx0 = -INFINITY, mx1 = -INFINITY;
#pragma unroll
        for (int nf = 0; nf < 8; nf++) {
            mx0 = fmaxf(mx0, fmaxf(sc[nf][0], sc[nf][1]));
            mx1 = fmaxf(mx1, fmaxf(sc[nf][2], sc[nf][3]));
        }
        mx0 = fmaxf(mx0, __shfl_xor_sync(0xffffffffu, mx0, 1));
        mx0 = fmaxf(mx0, __shfl_xor_sync(0xffffffffu, mx0, 2));
        mx1 = fmaxf(mx1, __shfl_xor_sync(0xffffffffu, mx1, 1));
        mx1 = fmaxf(mx1, __shfl_xor_sync(0xffffffffu, mx1, 2));

        float mn0 = fmaxf(m0, mx0), mn1 = fmaxf(m1, mx1);
        float a0 = __expf(m0 - mn0), a1 = __expf(m1 - mn1);
        float rs0 = 0.0f, rs1 = 0.0f;
#pragma unroll
        for (int nf = 0; nf < 8; nf++) {
            sc[nf][0] = __expf(sc[nf][0] - mn0);
            sc[nf][1] = __expf(sc[nf][1] - mn0);
            sc[nf][2] = __expf(sc[nf][2] - mn1);
            sc[nf][3] = __expf(sc[nf][3] - mn1);
            rs0 += sc[nf][0] + sc[nf][1];
            rs1 += sc[nf][2] + sc[nf][3];
        }
        rs0 += __shfl_xor_sync(0xffffffffu, rs0, 1);
        rs0 += __shfl_xor_sync(0xffffffffu, rs0, 2);
        rs1 += __shfl_xor_sync(0xffffffffu, rs1, 1);
        rs1 += __shfl_xor_sync(0xffffffffu, rs1, 2);
        l0s = l0s * a0 + rs0;
        l1s = l1s * a1 + rs1;
        m0 = mn0; m1 = mn1;
#pragma unroll
        for (int nf = 0; nf < 16; nf++) {
            o[nf][0] *= a0; o[nf][1] *= a0;
            o[nf][2] *= a1; o[nf][3] *= a1;
        }

        uint32_t ph[4][4], pl[4][4];
#pragma unroll
        for (int ks = 0; ks < 4; ks++) {
            split2(sc[2 * ks][0],     sc[2 * ks][1],     ph[ks][0], pl[ks][0]);
            split2(sc[2 * ks][2],     sc[2 * ks][3],     ph[ks][1], pl[ks][1]);
            split2(sc[2 * ks + 1][0], sc[2 * ks + 1][1], ph[ks][2], pl[ks][2]);
            split2(sc[2 * ks + 1][2], sc[2 * ks + 1][3], ph[ks][3], pl[ks][3]);
        }

#pragma unroll
        for (int nfp = 0; nfp < 8; nfp++) {
#pragma unroll
            for (int ks = 0; ks < 4; ks++) {
                uint32_t vAdr = stg + (uint32_t)(ks * 16) * FPITCH + lmV + nfp * 32;
                uint32_t vh0, vh1, vh2, vh3, vl0, vl1, vl2, vl3;
                ldsm4t(vAdr + FVH, vh0, vh1, vh2, vh3);
                ldsm4t(vAdr + FVL, vl0, vl1, vl2, vl3);
                mma_bf16_2(o[nfp * 2],     ph[ks], vh0, vh1);
                mma_bf16_2(o[nfp * 2 + 1], ph[ks], vh2, vh3);
                mma_bf16_2(o[nfp * 2],     ph[ks], vl0, vl1);
                mma_bf16_2(o[nfp * 2 + 1], ph[ks], vl2, vl3);
                mma_bf16_2(o[nfp * 2],     pl[ks], vh0, vh1);
                mma_bf16_2(o[nfp * 2 + 1], pl[ks], vh2, vh3);
            }
        }
        __syncthreads();
    }

    const float inv0 = 1.0f / l0s;
    const float inv1 = 1.0f / l1s;
    const int g = lane >> 2;
    const int tq = lane & 3;
    const int row0 = q0 + w * 16 + g;
    size_t base0 = ((size_t)(b * SEQ + row0)) * DIM + hoff + tq * 2;
    size_t base1 = base0 + (size_t)8 * DIM;
#pragma unroll
    for (int nf = 0; nf < 16; nf++) {
        uint32_t hi, lo;
        split2(o[nf][0] * inv0, o[nf][1] * inv0, hi, lo);
        *(uint32_t*)&g_ah[base0 + nf * 8] = hi;
        *(uint32_t*)&g_al[base0 + nf * 8] = lo;
        split2(o[nf][2] * inv1, o[nf][3] * inv1, hi, lo);
        *(uint32_t*)&g_ah[base1 + nf * 8] = hi;
        *(uint32_t*)&g_al[base1 + nf * 8] = lo;
    }
#undef LOADKV
}

// ---------------------------------------------------------------------------
// Launch
// ---------------------------------------------------------------------------
extern "C" void kernel_launch(void* const* d_in, const int* in_sizes, int n_in,
                              void* d_out, int out_size) {
    const float* x    = (const float*)d_in[0];
    const float* wq   = (const float*)d_in[1];
    const float* wk   = (const float*)d_in[2];
    const float* wv   = (const float*)d_in[3];
    const float* wo   = (const float*)d_in[4];
    const float* fcos = (const float*)d_in[5];
    const float* fsin = (const float*)d_in[6];
    float* out = (float*)d_out;

    __nv_bfloat16 *xh, *xl, *wqh, *wql, *wkh, *wkl, *wvh, *wvl, *woh, *wol;
    __nv_bfloat16 *qh, *ql, *kh, *kl, *vh, *vl, *ah, *al;
    cudaGetSymbolAddress((void**)&xh,  g_xh);
    cudaGetSymbolAddress((void**)&xl,  g_xl);
    cudaGetSymbolAddress((void**)&wqh, g_wqh);
    cudaGetSymbolAddress((void**)&wql, g_wql);
    cudaGetSymbolAddress((void**)&wkh, g_wkh);
    cudaGetSymbolAddress((void**)&wkl, g_wkl);
    cudaGetSymbolAddress((void**)&wvh, g_wvh);
    cudaGetSymbolAddress((void**)&wvl, g_wvl);
    cudaGetSymbolAddress((void**)&woh, g_woh);
    cudaGetSymbolAddress((void**)&wol, g_wol);
    cudaGetSymbolAddress((void**)&qh,  g_qh);
    cudaGetSymbolAddress((void**)&ql,  g_ql);
    cudaGetSymbolAddress((void**)&kh,  g_kh);
    cudaGetSymbolAddress((void**)&kl,  g_kl);
    cudaGetSymbolAddress((void**)&vh,  g_vh);
    cudaGetSymbolAddress((void**)&vl,  g_vl);
    cudaGetSymbolAddress((void**)&ah,  g_ah);
    cudaGetSymbolAddress((void**)&al,  g_al);

    cudaFuncSetAttribute(gemm_qkv, cudaFuncAttributeMaxDynamicSharedMemorySize,
                         GEMM_SMEM);
    cudaFuncSetAttribute(gemm_o, cudaFuncAttributeMaxDynamicSharedMemorySize,
                         GEMM_SMEM);
    cudaFuncSetAttribute(flash_mma, cudaFuncAttributeMaxDynamicSharedMemorySize,
                         FLASH_SMEM);

    split5_kernel<<<dim3(NELEM / 4 / 256, 5), 256>>>(x, wq, wk, wv, wo);

    dim3 ggrid(DIM / BN, MROWS / BM);   // (32, 32)
    gemm_qkv<<<ggrid, 256, GEMM_SMEM>>>(xh, xl, wqh, wql, qh, ql, fcos, fsin, 0);
    gemm_qkv<<<ggrid, 256, GEMM_SMEM>>>(xh, xl, wkh, wkl, kh, kl, fcos, fsin, 1);
    gemm_qkv<<<ggrid, 256, GEMM_SMEM>>>(xh, xl, wvh, wvl, vh, vl, fcos, fsin, 2);

    flash_mma<<<dim3(SEQ / 128, NHEAD, BATCH), 256, FLASH_SMEM>>>();

    gemm_o<<<ggrid, 256, GEMM_SMEM>>>(ah, al, woh, wol, out);
}

// round 11
// speedup vs baseline: 1.1664x; 1.0463x over previous
#include <cuda_runtime.h>
#include <cuda_bf16.h>
#include <math.h>
#include <stdint.h>

// Problem constants
#define BATCH 2
#define SEQ   2048
#define DIM   4096
#define NHEAD 32
#define HDIM  128
#define MROWS (BATCH * SEQ)   // 4096
#define NELEM (MROWS * DIM)   // 16777216

// pre-split bf16 scratch
__device__ __nv_bfloat16 g_xh[NELEM],  g_xl[NELEM];
__device__ __nv_bfloat16 g_wqh[NELEM], g_wql[NELEM];
__device__ __nv_bfloat16 g_wkh[NELEM], g_wkl[NELEM];
__device__ __nv_bfloat16 g_wvh[NELEM], g_wvl[NELEM];
__device__ __nv_bfloat16 g_woh[NELEM], g_wol[NELEM];
__device__ __nv_bfloat16 g_qh[NELEM],  g_ql[NELEM];
__device__ __nv_bfloat16 g_kh[NELEM],  g_kl[NELEM];
__device__ __nv_bfloat16 g_vh[NELEM],  g_vl[NELEM];
__device__ __nv_bfloat16 g_ah[NELEM],  g_al[NELEM];

// ---------------------------------------------------------------------------
// Helpers
// ---------------------------------------------------------------------------
__device__ __forceinline__ uint32_t smem_u32(const void* p) {
    uint32_t a;
    asm("{ .reg .u64 t; cvta.to.shared.u64 t, %1; cvt.u32.u64 %0, t; }"
        : "=r"(a) : "l"(p));
    return a;
}

__device__ __forceinline__ void cpa16(uint32_t dst, const void* src) {
    asm volatile("cp.async.cg.shared.global [%0], [%1], 16;"
                 :: "r"(dst), "l"(src));
}
#define CP_COMMIT() asm volatile("cp.async.commit_group;" ::: "memory")
#define CP_WAIT(n)  asm volatile("cp.async.wait_group " #n ";" ::: "memory")

__device__ __forceinline__ void ldsm4(uint32_t addr, uint32_t& r0, uint32_t& r1,
                                      uint32_t& r2, uint32_t& r3) {
    asm volatile("ldmatrix.sync.aligned.m8n8.x4.shared.b16 {%0,%1,%2,%3}, [%4];"
                 : "=r"(r0), "=r"(r1), "=r"(r2), "=r"(r3) : "r"(addr));
}
__device__ __forceinline__ void ldsm4t(uint32_t addr, uint32_t& r0, uint32_t& r1,
                                       uint32_t& r2, uint32_t& r3) {
    asm volatile("ldmatrix.sync.aligned.m8n8.x4.trans.shared.b16 {%0,%1,%2,%3}, [%4];"
                 : "=r"(r0), "=r"(r1), "=r"(r2), "=r"(r3) : "r"(addr));
}

__device__ __forceinline__ void mma_bf16(float* c, const uint32_t* a,
                                         const uint32_t* b) {
    asm volatile(
        "mma.sync.aligned.m16n8k16.row.col.f32.bf16.bf16.f32 "
        "{%0,%1,%2,%3}, {%4,%5,%6,%7}, {%8,%9}, {%0,%1,%2,%3};"
        : "+f"(c[0]), "+f"(c[1]), "+f"(c[2]), "+f"(c[3])
        : "r"(a[0]), "r"(a[1]), "r"(a[2]), "r"(a[3]), "r"(b[0]), "r"(b[1]));
}
__device__ __forceinline__ void mma_bf16_2(float* c, const uint32_t* a,
                                           uint32_t b0, uint32_t b1) {
    asm volatile(
        "mma.sync.aligned.m16n8k16.row.col.f32.bf16.bf16.f32 "
        "{%0,%1,%2,%3}, {%4,%5,%6,%7}, {%8,%9}, {%0,%1,%2,%3};"
        : "+f"(c[0]), "+f"(c[1]), "+f"(c[2]), "+f"(c[3])
        : "r"(a[0]), "r"(a[1]), "r"(a[2]), "r"(a[3]), "r"(b0), "r"(b1));
}

__device__ __forceinline__ uint32_t packbf(__nv_bfloat16 a, __nv_bfloat16 b) {
    return ((uint32_t)__bfloat16_as_ushort(b) << 16) | __bfloat16_as_ushort(a);
}
__device__ __forceinline__ void split2(float x, float y, uint32_t& hi, uint32_t& lo) {
    __nv_bfloat16 hx = __float2bfloat16(x);
    __nv_bfloat16 hy = __float2bfloat16(y);
    hi = packbf(hx, hy);
    lo = packbf(__float2bfloat16(x - __bfloat162float(hx)),
                __float2bfloat16(y - __bfloat162float(hy)));
}

// ---------------------------------------------------------------------------
// Merged split kernel (unchanged from R10)
// ---------------------------------------------------------------------------
__global__ __launch_bounds__(256) void split5_kernel(
    const float* __restrict__ s0, const float* __restrict__ s1,
    const float* __restrict__ s2, const float* __restrict__ s3,
    const float* __restrict__ s4) {
    int i = blockIdx.x * blockDim.x + threadIdx.x;
    const float* src;
    __nv_bfloat16 *dh, *dl;
    switch (blockIdx.y) {
        case 0:  src = s0; dh = g_xh;  dl = g_xl;  break;
        case 1:  src = s1; dh = g_wqh; dl = g_wql; break;
        case 2:  src = s2; dh = g_wkh; dl = g_wkl; break;
        case 3:  src = s3; dh = g_wvh; dl = g_wvl; break;
        default: src = s4; dh = g_woh; dl = g_wol; break;
    }
    float4 v = ((const float4*)src)[i];
    uint32_t h0, l0, h1, l1;
    split2(v.x, v.y, h0, l0);
    split2(v.z, v.w, h1, l1);
    ((uint2*)dh)[i] = make_uint2(h0, h1);
    ((uint2*)dl)[i] = make_uint2(l0, l1);
}

// ---------------------------------------------------------------------------
// bf16x3 GEMM core v2: 128x128 tile, BK=32, **512 threads / 16 warps (4x4,
// warp tile 32x32)** -> 4 warps per SMSP to fill HMMA issue slots.
// 4-stage cp.async pipeline.
// ---------------------------------------------------------------------------
#define BM 128
#define BN 128
#define BK 32
#define NKC (DIM / BK)   // 128
#define PITCHB 80

#define OFF_AHI 0
#define OFF_ALO 10240
#define OFF_BHI 20480
#define OFF_BLO 30720
#define STAGE_BYTES 40960
#define GEMM_SMEM (4 * STAGE_BYTES)   // 163840
#define GTHREADS 512

// per chunk: 4 tiles x 512 segs(16B) = 2048 cp.async / 512 thr = 4 per thread
#define ISSUE(kc, stg)                                                        \
    {                                                                         \
        uint32_t sb = sbase + (uint32_t)(stg) * STAGE_BYTES;                  \
        size_t gk = (size_t)(kc) * 64;                                        \
        int row = tid >> 2;                                                   \
        int off = (tid & 3) * 16;                                             \
        uint32_t so = (uint32_t)row * PITCHB + off;                           \
        size_t go = (size_t)row * (DIM * 2) + gk + off;                       \
        cpa16(sb + OFF_AHI + so, Ahb + go);                                   \
        cpa16(sb + OFF_ALO + so, Alb + go);                                   \
        cpa16(sb + OFF_BHI + so, Bhb + go);                                   \
        cpa16(sb + OFF_BLO + so, Blb + go);                                   \
        CP_COMMIT();                                                          \
    }

#define GEMM_MAINLOOP(Ahb, Alb, Bhb, Blb)                                     \
    const uint32_t lm_off = (uint32_t)(lane & 15) * PITCHB + (lane >> 4) * 16;\
    const uint32_t aAdr0 = (uint32_t)(wm * 32) * PITCHB + lm_off;             \
    const uint32_t bAdr0 = (uint32_t)(wn * 32) * PITCHB + lm_off;             \
    ISSUE(0, 0); ISSUE(1, 1); ISSUE(2, 2);                                    \
    for (int kc = 0; kc < NKC; kc++) {                                        \
        CP_WAIT(2);                                                           \
        __syncthreads();                                                      \
        if (kc + 3 < NKC) { ISSUE(kc + 3, (kc + 3) & 3); }                    \
        else { CP_COMMIT(); }                                                 \
        const uint32_t stg = sbase + (uint32_t)(kc & 3) * STAGE_BYTES;        \
        const uint32_t aHi = stg + OFF_AHI + aAdr0;                           \
        const uint32_t aLo = stg + OFF_ALO + aAdr0;                           \
        const uint32_t bHi = stg + OFF_BHI + bAdr0;                           \
        const uint32_t bLo = stg + OFF_BLO + bAdr0;                           \
        _Pragma("unroll")                                                     \
        for (int s = 0; s < 2; s++) {                                         \
            uint32_t aF[2][4], bH[4][2], bL[4][2];                            \
            _Pragma("unroll")                                                 \
            for (int mi = 0; mi < 2; mi++)                                    \
                ldsm4(aHi + mi * (16 * PITCHB) + s * 32,                      \
                      aF[mi][0], aF[mi][1], aF[mi][2], aF[mi][3]);            \
            _Pragma("unroll")                                                 \
            for (int nj = 0; nj < 2; nj++) {                                  \
                uint32_t r0, r1, r2, r3;                                      \
                ldsm4(bHi + nj * (16 * PITCHB) + s * 32, r0, r1, r2, r3);     \
                bH[nj * 2][0] = r0; bH[nj * 2 + 1][0] = r1;                   \
                bH[nj * 2][1] = r2; bH[nj * 2 + 1][1] = r3;                   \
                ldsm4(bLo + nj * (16 * PITCHB) + s * 32, r0, r1, r2, r3);     \
                bL[nj * 2][0] = r0; bL[nj * 2 + 1][0] = r1;                   \
                bL[nj * 2][1] = r2; bL[nj * 2 + 1][1] = r3;                   \
            }                                                                 \
            _Pragma("unroll")                                                 \
            for (int mi = 0; mi < 2; mi++)                                    \
                _Pragma("unroll")                                             \
                for (int nf = 0; nf < 4; nf++)                                \
                    mma_bf16(acc[mi][nf], aF[mi], bH[nf]);                    \
            _Pragma("unroll")                                                 \
            for (int mi = 0; mi < 2; mi++)                                    \
                _Pragma("unroll")                                             \
                for (int nf = 0; nf < 4; nf++)                                \
                    mma_bf16(acc[mi][nf], aF[mi], bL[nf]);                    \
            _Pragma("unroll")                                                 \
            for (int mi = 0; mi < 2; mi++)                                    \
                ldsm4(aLo + mi * (16 * PITCHB) + s * 32,                      \
                      aF[mi][0], aF[mi][1], aF[mi][2], aF[mi][3]);            \
            _Pragma("unroll")                                                 \
            for (int mi = 0; mi < 2; mi++)                                    \
                _Pragma("unroll")                                             \
                for (int nf = 0; nf < 4; nf++)                                \
                    mma_bf16(acc[mi][nf], aF[mi], bH[nf]);                    \
        }                                                                     \
        __syncthreads();                                                      \
    }

// ---------------------------------------------------------------------------
// QKV GEMM (one launch per z). RoPE+scale fused with smem-staged trig.
// ---------------------------------------------------------------------------
#define TRIG_PITCH 66

__global__ __launch_bounds__(GTHREADS, 1)
void gemm_qkv(const __nv_bfloat16* __restrict__ Xh,
              const __nv_bfloat16* __restrict__ Xl,
              const __nv_bfloat16* __restrict__ Wh,
              const __nv_bfloat16* __restrict__ Wl,
              __nv_bfloat16* __restrict__ OH,
              __nv_bfloat16* __restrict__ OL,
              const float* __restrict__ fcos, const float* __restrict__ fsin,
              int z) {
    extern __shared__ char smem_raw[];
    const uint32_t sbase = smem_u32(smem_raw);
    const int tid  = threadIdx.x;
    const int wid  = tid >> 5;
    const int lane = tid & 31;
    const int wm   = wid >> 2;        // 0..3
    const int wn   = wid & 3;         // 0..3
    const int m0   = blockIdx.y * BM;
    const int n0   = blockIdx.x * BN;

    const char* Ahb = (const char*)(Xh + (size_t)m0 * DIM);
    const char* Alb = (const char*)(Xl + (size_t)m0 * DIM);
    const char* Bhb = (const char*)(Wh + (size_t)n0 * DIM);
    const char* Blb = (const char*)(Wl + (size_t)n0 * DIM);

    float acc[2][4][4];
#pragma unroll
    for (int i = 0; i < 2; i++)
#pragma unroll
        for (int j = 0; j < 4; j++)
#pragma unroll
            for (int k = 0; k < 4; k++) acc[i][j][k] = 0.0f;

    GEMM_MAINLOOP(Ahb, Alb, Bhb, Blb)

    // Stage trig table into dead pipeline smem
    float2* trig = (float2*)smem_raw;
    if (z < 2) {
        for (int i = tid; i < 128 * 64; i += GTHREADS) {
            int sl = i >> 6, j = i & 63;
            int s = (m0 + sl) & (SEQ - 1);
            trig[sl * TRIG_PITCH + j] = make_float2(fcos[s * 64 + j],
                                                    fsin[s * 64 + j]);
        }
        __syncthreads();
    }

    const float qscale = 0.08838834764831845f;
#pragma unroll
    for (int mi = 0; mi < 2; mi++) {
#pragma unroll
        for (int nf = 0; nf < 4; nf++) {
            int rl  = wm * 32 + mi * 16 + (lane >> 2);
            int row = m0 + rl;
            int col = n0 + wn * 32 + nf * 8 + (lane & 3) * 2;
            float c0 = acc[mi][nf][0], c1 = acc[mi][nf][1];
            float c2 = acc[mi][nf][2], c3 = acc[mi][nf][3];
            if (z < 2) {
                int j = (wn * 32 + nf * 8) / 2 + (lane & 3);
                float2 tA = trig[rl * TRIG_PITCH + j];
                float2 tB = trig[(rl + 8) * TRIG_PITCH + j];
                float r0 = c0 * tA.x - c1 * tA.y, i0 = c0 * tA.y + c1 * tA.x;
                float r1 = c2 * tB.x - c3 * tB.y, i1 = c2 * tB.y + c3 * tB.x;
                if (z == 0) { r0 *= qscale; i0 *= qscale; r1 *= qscale; i1 *= qscale; }
                c0 = r0; c1 = i0; c2 = r1; c3 = i1;
            }
            uint32_t hi, lo;
            split2(c0, c1, hi, lo);
            *(uint32_t*)&OH[(size_t)row * DIM + col] = hi;
            *(uint32_t*)&OL[(size_t)row * DIM + col] = lo;
            split2(c2, c3, hi, lo);
            *(uint32_t*)&OH[(size_t)(row + 8) * DIM + col] = hi;
            *(uint32_t*)&OL[(size_t)(row + 8) * DIM + col] = lo;
        }
    }
}

// ---------------------------------------------------------------------------
// O-projection GEMM (512 threads)
// ---------------------------------------------------------------------------
__global__ __launch_bounds__(GTHREADS, 1)
void gemm_o(const __nv_bfloat16* __restrict__ Ah,
            const __nv_bfloat16* __restrict__ Al,
            const __nv_bfloat16* __restrict__ Bh,
            const __nv_bfloat16* __restrict__ Bl,
            float* __restrict__ C) {
    extern __shared__ char smem_raw[];
    const uint32_t sbase = smem_u32(smem_raw);
    const int tid  = threadIdx.x;
    const int wid  = tid >> 5;
    const int lane = tid & 31;
    const int wm   = wid >> 2;
    const int wn   = wid & 3;
    const int m0   = blockIdx.y * BM;
    const int n0   = blockIdx.x * BN;

    const char* Ahb = (const char*)(Ah + (size_t)m0 * DIM);
    const char* Alb = (const char*)(Al + (size_t)m0 * DIM);
    const char* Bhb = (const char*)(Bh + (size_t)n0 * DIM);
    const char* Blb = (const char*)(Bl + (size_t)n0 * DIM);

    float acc[2][4][4];
#pragma unroll
    for (int i = 0; i < 2; i++)
#pragma unroll
        for (int j = 0; j < 4; j++)
#pragma unroll
            for (int k = 0; k < 4; k++) acc[i][j][k] = 0.0f;

    GEMM_MAINLOOP(Ahb, Alb, Bhb, Blb)

#pragma unroll
    for (int mi = 0; mi < 2; mi++) {
#pragma unroll
        for (int nf = 0; nf < 4; nf++) {
            int row = m0 + wm * 32 + mi * 16 + (lane >> 2);
            int col = n0 + wn * 32 + nf * 8 + (lane & 3) * 2;
            *(float2*)&C[(size_t)row * DIM + col] =
                make_float2(acc[mi][nf][0], acc[mi][nf][1]);
            *(float2*)&C[(size_t)(row + 8) * DIM + col] =
                make_float2(acc[mi][nf][2], acc[mi][nf][3]);
        }
    }
}

// ---------------------------------------------------------------------------
// Flash attention (R5 exactly — unchanged this round)
// ---------------------------------------------------------------------------
#define FPITCH 272
#define FQH 0
#define FQL (128 * FPITCH)
#define FSTG0 (2 * 128 * FPITCH)
#define FKH 0
#define FKL (64 * FPITCH)
#define FVH (128 * FPITCH)
#define FVL (192 * FPITCH)
#define FSTAGE (256 * FPITCH)
#define FLASH_SMEM (FSTG0 + 2 * FSTAGE)

__global__ __launch_bounds__(256)
void flash_mma() {
    extern __shared__ char smem_raw[];
    const uint32_t sbase = smem_u32(smem_raw);
    const int tid  = threadIdx.x;
    const int w    = tid >> 5;
    const int lane = tid & 31;
    const int qt = blockIdx.x;
    const int h  = blockIdx.y;
    const int b  = blockIdx.z;
    const int q0 = qt * 128;
    const size_t hoff = (size_t)h * HDIM;

    const char* khb = (const char*)g_kh;
    const char* klb = (const char*)g_kl;
    const char* vhb = (const char*)g_vh;
    const char* vlb = (const char*)g_vl;

    {
        const char* qhb = (const char*)g_qh;
        const char* qlb = (const char*)g_ql;
        for (int i = tid; i < 2048; i += 256) {
            int r = i >> 4, sg = (i & 15) * 16;
            size_t go = ((size_t)(b * SEQ + q0 + r) * DIM + hoff) * 2 + sg;
            uint32_t so = (uint32_t)r * FPITCH + sg;
            *(uint4*)(smem_raw + FQH + so) = *(const uint4*)(qhb + go);
            *(uint4*)(smem_raw + FQL + so) = *(const uint4*)(qlb + go);
        }
    }

#define LOADKV(t, stg)                                                        \
    {                                                                         \
        uint32_t sp = sbase + FSTG0 + (uint32_t)(stg) * FSTAGE;               \
        const int j0 = (t) * 64;                                              \
        _Pragma("unroll")                                                     \
        for (int u = 0; u < 4; u++) {                                         \
            int seg = tid + u * 256;                                          \
            int row = seg >> 4;                                               \
            int off = (seg & 15) * 16;                                        \
            uint32_t so = (uint32_t)row * FPITCH + off;                       \
            size_t go = ((size_t)(b * SEQ + j0 + row) * DIM + hoff) * 2 + off;\
            cpa16(sp + FKH + so, khb + go);                                   \
            cpa16(sp + FKL + so, klb + go);                                   \
            cpa16(sp + FVH + so, vhb + go);                                   \
            cpa16(sp + FVL + so, vlb + go);                                   \
        }                                                                     \
        CP_COMMIT();                                                          \
    }

    LOADKV(0, 0);

    float o[16][4];
#pragma unroll
    for (int nf = 0; nf < 16; nf++)
#pragma unroll
        for (int k = 0; k < 4; k++) o[nf][k] = 0.0f;
    float m0 = -INFINITY, m1 = -INFINITY, l0s = 0.0f, l1s = 0.0f;

    const uint32_t lmA = (uint32_t)(lane & 15) * FPITCH + (lane >> 4) * 16;
    const uint32_t qAdr = sbase + (uint32_t)(w * 16) * FPITCH + lmA;
    const uint32_t lmV = (uint32_t)(((lane >> 3) & 1) * 8 + (lane & 7)) * FPITCH
                         + (lane >> 4) * 16;

    for (int t = 0; t < 32; t++) {
        const int cur = t & 1;
        CP_WAIT(0);
        __syncthreads();
        if (t + 1 < 32) { LOADKV(t + 1, 1 - cur); }

        const uint32_t stg = sbase + FSTG0 + (uint32_t)cur * FSTAGE;

        float sc[8][4];
#pragma unroll
        for (int nf = 0; nf < 8; nf++)
#pragma unroll
            for (int k = 0; k < 4; k++) sc[nf][k] = 0.0f;

#pragma unroll
        for (int ks = 0; ks < 8; ks++) {
            uint32_t qh[4], ql[4];
            ldsm4(qAdr + FQH + ks * 32, qh[0], qh[1], qh[2], qh[3]);
            ldsm4(qAdr + FQL + ks * 32, ql[0], ql[1], ql[2], ql[3]);
#pragma unroll
            for (int nfp = 0; nfp < 4; nfp++) {
                uint32_t kAdr = stg + (uint32_t)(nfp * 16) * FPITCH + lmA + ks * 32;
                uint32_t kh0, kh1, kh2, kh3, kl0, kl1, kl2, kl3;
                ldsm4(kAdr + FKH, kh0, kh1, kh2, kh3);
                ldsm4(kAdr + FKL, kl0, kl1, kl2, kl3);
                mma_bf16_2(sc[nfp * 2],     qh, kh0, kh2);
                mma_bf16_2(sc[nfp * 2 + 1], qh, kh1, kh3);
                mma_bf16_2(sc[nfp * 2],     qh, kl0, kl2);
                mma_bf16_2(sc[nfp * 2 + 1], qh, kl1, kl3);
                mma_bf16_2(sc[nfp * 2],     ql, kh0, kh2);
                mma_bf16_2(sc[nfp * 2 + 1], ql, kh1, kh3);
            }
        }

        float mx0 = -INFINITY, mx1 = -INFINITY;
#pragma unroll
        for (int nf = 0; nf < 8; nf++) {
            mx0 = fmaxf(mx0, fmaxf(sc[nf][0], sc[nf][1]));
            mx1 = fmaxf(mx1, fmaxf(sc[nf][2], sc[nf][3]));
        }
        mx0 = fmaxf(mx0, __shfl_xor_sync(0xffffffffu, mx0, 1));
        mx0 = fmaxf(mx0, __shfl_xor_sync(0xffffffffu, mx0, 2));
        mx1 = fmaxf(mx1, __shfl_xor_sync(0xffffffffu, mx1, 1));
        mx1 = fmaxf(mx1, __shfl_xor_sync(0xffffffffu, mx1, 2));

        float mn0 = fmaxf(m0, mx0), mn1 = fmaxf(m1, mx1);
        float a0 = __expf(m0 - mn0), a1 = __expf(m1 - mn1);
        float rs0 = 0.0f, rs1 = 0.0f;
#pragma unroll
        for (int nf = 0; nf < 8; nf++) {
            sc[nf][0] = __expf(sc[nf][0] - mn0);
            sc[nf][1] = __expf(sc[nf][1] - mn0);
            sc[nf][2] = __expf(sc[nf][2] - mn1);
            sc[nf][3] = __expf(sc[nf][3] - mn1);
            rs0 += sc[nf][0] + sc[nf][1];
            rs1 += sc[nf][2] + sc[nf][3];
        }
        rs0 += __shfl_xor_sync(0xffffffffu, rs0, 1);
        rs0 += __shfl_xor_sync(0xffffffffu, rs0, 2);
        rs1 += __shfl_xor_sync(0xffffffffu, rs1, 1);
        rs1 += __shfl_xor_sync(0xffffffffu, rs1, 2);
        l0s = l0s * a0 + rs0;
        l1s = l1s * a1 + rs1;
        m0 = mn0; m1 = mn1;
#pragma unroll
        for (int nf = 0; nf < 16; nf++) {
            o[nf][0] *= a0; o[nf][1] *= a0;
            o[nf][2] *= a1; o[nf][3] *= a1;
        }

        uint32_t ph[4][4], pl[4][4];
#pragma unroll
        for (int ks = 0; ks < 4; ks++) {
            split2(sc[2 * ks][0],     sc[2 * ks][1],     ph[ks][0], pl[ks][0]);
            split2(sc[2 * ks][2],     sc[2 * ks][3],     ph[ks][1], pl[ks][1]);
            split2(sc[2 * ks + 1][0], sc[2 * ks + 1][1], ph[ks][2], pl[ks][2]);
            split2(sc[2 * ks + 1][2], sc[2 * ks + 1][3], ph[ks][3], pl[ks][3]);
        }

#pragma unroll
        for (int nfp = 0; nfp < 8; nfp++) {
#pragma unroll
            for (int ks = 0; ks < 4; ks++) {
                uint32_t vAdr = stg + (uint32_t)(ks * 16) * FPITCH + lmV + nfp * 32;
                uint32_t vh0, vh1, vh2, vh3, vl0, vl1, vl2, vl3;
                ldsm4t(vAdr + FVH, vh0, vh1, vh2, vh3);
                ldsm4t(vAdr + FVL, vl0, vl1, vl2, vl3);
                mma_bf16_2(o[nfp * 2],     ph[ks], vh0, vh1);
                mma_bf16_2(o[nfp * 2 + 1], ph[ks], vh2, vh3);
                mma_bf16_2(o[nfp * 2],     ph[ks], vl0, vl1);
                mma_bf16_2(o[nfp * 2 + 1], ph[ks], vl2, vl3);
                mma_bf16_2(o[nfp * 2],     pl[ks], vh0, vh1);
                mma_bf16_2(o[nfp * 2 + 1], pl[ks], vh2, vh3);
            }
        }
        __syncthreads();
    }

    const float inv0 = 1.0f / l0s;
    const float inv1 = 1.0f / l1s;
    const int g = lane >> 2;
    const int tq = lane & 3;
    const int row0 = q0 + w * 16 + g;
    size_t base0 = ((size_t)(b * SEQ + row0)) * DIM + hoff + tq * 2;
    size_t base1 = base0 + (size_t)8 * DIM;
#pragma unroll
    for (int nf = 0; nf < 16; nf++) {
        uint32_t hi, lo;
        split2(o[nf][0] * inv0, o[nf][1] * inv0, hi, lo);
        *(uint32_t*)&g_ah[base0 + nf * 8] = hi;
        *(uint32_t*)&g_al[base0 + nf * 8] = lo;
        split2(o[nf][2] * inv1, o[nf][3] * inv1, hi, lo);
        *(uint32_t*)&g_ah[base1 + nf * 8] = hi;
        *(uint32_t*)&g_al[base1 + nf * 8] = lo;
    }
#undef LOADKV
}

// ---------------------------------------------------------------------------
// Launch
// ---------------------------------------------------------------------------
extern "C" void kernel_launch(void* const* d_in, const int* in_sizes, int n_in,
                              void* d_out, int out_size) {
    const float* x    = (const float*)d_in[0];
    const float* wq   = (const float*)d_in[1];
    const float* wk   = (const float*)d_in[2];
    const float* wv   = (const float*)d_in[3];
    const float* wo   = (const float*)d_in[4];
    const float* fcos = (const float*)d_in[5];
    const float* fsin = (const float*)d_in[6];
    float* out = (float*)d_out;

    __nv_bfloat16 *xh, *xl, *wqh, *wql, *wkh, *wkl, *wvh, *wvl, *woh, *wol;
    __nv_bfloat16 *qh, *ql, *kh, *kl, *vh, *vl, *ah, *al;
    cudaGetSymbolAddress((void**)&xh,  g_xh);
    cudaGetSymbolAddress((void**)&xl,  g_xl);
    cudaGetSymbolAddress((void**)&wqh, g_wqh);
    cudaGetSymbolAddress((void**)&wql, g_wql);
    cudaGetSymbolAddress((void**)&wkh, g_wkh);
    cudaGetSymbolAddress((void**)&wkl, g_wkl);
    cudaGetSymbolAddress((void**)&wvh, g_wvh);
    cudaGetSymbolAddress((void**)&wvl, g_wvl);
    cudaGetSymbolAddress((void**)&woh, g_woh);
    cudaGetSymbolAddress((void**)&wol, g_wol);
    cudaGetSymbolAddress((void**)&qh,  g_qh);
    cudaGetSymbolAddress((void**)&ql,  g_ql);
    cudaGetSymbolAddress((void**)&kh,  g_kh);
    cudaGetSymbolAddress((void**)&kl,  g_kl);
    cudaGetSymbolAddress((void**)&vh,  g_vh);
    cudaGetSymbolAddress((void**)&vl,  g_vl);
    cudaGetSymbolAddress((void**)&ah,  g_ah);
    cudaGetSymbolAddress((void**)&al,  g_al);

    cudaFuncSetAttribute(gemm_qkv, cudaFuncAttributeMaxDynamicSharedMemorySize,
                         GEMM_SMEM);
    cudaFuncSetAttribute(gemm_o, cudaFuncAttributeMaxDynamicSharedMemorySize,
                         GEMM_SMEM);
    cudaFuncSetAttribute(flash_mma, cudaFuncAttributeMaxDynamicSharedMemorySize,
                         FLASH_SMEM);

    split5_kernel<<<dim3(NELEM / 4 / 256, 5), 256>>>(x, wq, wk, wv, wo);

    dim3 ggrid(DIM / BN, MROWS / BM);   // (32, 32)
    gemm_qkv<<<ggrid, GTHREADS, GEMM_SMEM>>>(xh, xl, wqh, wql, qh, ql, fcos, fsin, 0);
    gemm_qkv<<<ggrid, GTHREADS, GEMM_SMEM>>>(xh, xl, wkh, wkl, kh, kl, fcos, fsin, 1);
    gemm_qkv<<<ggrid, GTHREADS, GEMM_SMEM>>>(xh, xl, wvh, wvl, vh, vl, fcos, fsin, 2);

    flash_mma<<<dim3(SEQ / 128, NHEAD, BATCH), 256, FLASH_SMEM>>>();

    gemm_o<<<ggrid, GTHREADS, GEMM_SMEM>>>(ah, al, woh, wol, out);
}